// round 1
// baseline (speedup 1.0000x reference)
#include <cuda_runtime.h>
#include <cstdint>
#include <math.h>

// Problem constants (fixed by the dataset)
#define NNODES 50000
#define HID 128
#define NH 4
#define DKH 32

// ---------------------------------------------------------------------------
// Scratch: __device__ globals (no allocation allowed in kernel_launch)
// ---------------------------------------------------------------------------
__device__ float g_q[2][NNODES * HID];     // q projections per node type
__device__ float g_k[3][NNODES * HID];     // rel_att-folded k per relation
__device__ float g_v[3][NNODES * HID];     // rel_msg-folded v per relation
__device__ float g_z[3][NNODES * NH];      // softmax denominators per relation
__device__ float g_agg[3][NNODES * HID];   // unnormalized message sums
__device__ float g_tm[2][NNODES * HID];    // combined per-type means
__device__ float g_Wc[6][HID * HID];       // combined weights: m = r*2 + (0=k,1=v)
__device__ float g_bc[6][HID];             // combined biases

// ---------------------------------------------------------------------------
// Zero a float buffer (float4 vectorized, grid-stride)
// ---------------------------------------------------------------------------
__global__ void zero_kernel(float* __restrict__ p, int n4) {
    int i = blockIdx.x * blockDim.x + threadIdx.x;
    int stride = gridDim.x * blockDim.x;
    float4 zz = make_float4(0.f, 0.f, 0.f, 0.f);
    for (; i < n4; i += stride) ((float4*)p)[i] = zz;
}

// ---------------------------------------------------------------------------
// Precompute combined weights: Wc[m] = Wbase[s] @ blockdiag_h(rel[r,h])
// grid: (6, 129). blockIdx.y == 128 handles the bias row.
// ---------------------------------------------------------------------------
__global__ void prep_comb(const float* __restrict__ Wk, const float* __restrict__ bk,
                          const float* __restrict__ Wv, const float* __restrict__ bv,
                          const float* __restrict__ rel_att, const float* __restrict__ rel_msg) {
    int m = blockIdx.x;          // 0..5
    int r = m >> 1;
    int kind = m & 1;            // 0 = attention (k path), 1 = message (v path)
    int s = (r == 0) ? 0 : 1;    // RELS src types: r0->0, r1->1, r2->1
    const float* Wbase = kind ? Wv : Wk;
    const float* bbase = kind ? bv : bk;
    const float* rel   = kind ? rel_msg : rel_att;

    int c = blockIdx.y;          // input row (or 128 == bias)
    int j = threadIdx.x;         // output column 0..127
    int h = j >> 5;
    int jj = j & 31;
    const float* A = rel + ((size_t)r * NH + h) * DKH * DKH;  // [32][32]

    float sum = 0.f;
    if (c < HID) {
        const float* wrow = Wbase + (size_t)s * HID * HID + (size_t)c * HID + h * DKH;
        #pragma unroll
        for (int i = 0; i < DKH; i++) sum = fmaf(wrow[i], A[i * DKH + jj], sum);
        g_Wc[m][c * HID + j] = sum;
    } else {
        const float* brow = bbase + s * HID + h * DKH;
        #pragma unroll
        for (int i = 0; i < DKH; i++) sum = fmaf(brow[i], A[i * DKH + jj], sum);
        g_bc[m][j] = sum;
    }
}

// ---------------------------------------------------------------------------
// GEMM: C[M,128] = A[M,128] @ W[128,128] + bias, optional skip-blend epilogue:
//   C = (A@W + b) * sigmoid(*skipv) + res * (1 - sigmoid(*skipv))
// Block tile 128x128, 256 threads, 8x8 register tile, BK=32.
// ---------------------------------------------------------------------------
__global__ __launch_bounds__(256) void gemm_fused(
    const float* __restrict__ A, const float* __restrict__ W,
    const float* __restrict__ bias, float* __restrict__ C,
    int M, const float* __restrict__ skipv, const float* __restrict__ res) {
    __shared__ float As[32][132];   // A^T tile: As[k][row], padded
    __shared__ float Ws[32][128];   // W tile:   Ws[k][col]

    int tid = threadIdx.x;
    int tx = tid & 15, ty = tid >> 4;
    int row0 = blockIdx.x * 128;

    float acc[8][8];
    #pragma unroll
    for (int u = 0; u < 8; u++)
        #pragma unroll
        for (int v = 0; v < 8; v++) acc[u][v] = 0.f;

    for (int k0 = 0; k0 < 128; k0 += 32) {
        // Load A tile (128 rows x 32 k), transposed into smem. 1024 float4s.
        #pragma unroll
        for (int it = 0; it < 4; it++) {
            int idx = tid + it * 256;
            int r = idx >> 3;
            int kk = (idx & 7) << 2;
            int grow = row0 + r;
            float4 av = make_float4(0.f, 0.f, 0.f, 0.f);
            if (grow < M) av = *(const float4*)(A + (size_t)grow * 128 + k0 + kk);
            As[kk + 0][r] = av.x; As[kk + 1][r] = av.y;
            As[kk + 2][r] = av.z; As[kk + 3][r] = av.w;
        }
        // Load W tile (32 k x 128 cols)
        #pragma unroll
        for (int it = 0; it < 4; it++) {
            int idx = tid + it * 256;
            int kk = idx >> 5;
            int c4 = (idx & 31) << 2;
            *(float4*)&Ws[kk][c4] = *(const float4*)(W + (size_t)(k0 + kk) * 128 + c4);
        }
        __syncthreads();

        #pragma unroll
        for (int k = 0; k < 32; k++) {
            float a[8], b[8];
            *(float4*)&a[0] = *(float4*)&As[k][ty * 8];
            *(float4*)&a[4] = *(float4*)&As[k][ty * 8 + 4];
            *(float4*)&b[0] = *(float4*)&Ws[k][tx * 8];
            *(float4*)&b[4] = *(float4*)&Ws[k][tx * 8 + 4];
            #pragma unroll
            for (int u = 0; u < 8; u++)
                #pragma unroll
                for (int v = 0; v < 8; v++)
                    acc[u][v] = fmaf(a[u], b[v], acc[u][v]);
        }
        __syncthreads();
    }

    float alpha = 1.f, beta = 0.f;
    if (skipv) {
        float sv = *skipv;
        alpha = 1.f / (1.f + expf(-sv));
        beta = 1.f - alpha;
    }

    #pragma unroll
    for (int u = 0; u < 8; u++) {
        int row = row0 + ty * 8 + u;
        if (row >= M) continue;
        #pragma unroll
        for (int v = 0; v < 8; v += 4) {
            int col = tx * 8 + v;
            float4 o;
            o.x = acc[u][v + 0] + bias[col + 0];
            o.y = acc[u][v + 1] + bias[col + 1];
            o.z = acc[u][v + 2] + bias[col + 2];
            o.w = acc[u][v + 3] + bias[col + 3];
            if (res) {
                float4 rv = *(const float4*)(res + (size_t)row * 128 + col);
                o.x = o.x * alpha + rv.x * beta;
                o.y = o.y * alpha + rv.y * beta;
                o.z = o.z * alpha + rv.z * beta;
                o.w = o.w * alpha + rv.w * beta;
            }
            *(float4*)(C + (size_t)row * 128 + col) = o;
        }
    }
}

// ---------------------------------------------------------------------------
// Edge kernel: one warp per edge. Computes per-head attention score, exp,
// accumulates z[dst,h] and the unnormalized message e * v'[src] into agg[dst].
// Softmax normalization (divide by z) is deferred to the combine kernel —
// mathematically identical to the max-subtracted reference softmax.
// ---------------------------------------------------------------------------
__global__ __launch_bounds__(256) void edge_kernel(
    const int* __restrict__ src, const int* __restrict__ dst, int E,
    const float* __restrict__ q, const float* __restrict__ kb,
    const float* __restrict__ vb, const float* __restrict__ pri,
    float* __restrict__ z, float* __restrict__ agg) {
    int gtid = blockIdx.x * blockDim.x + threadIdx.x;
    int e = gtid >> 5;
    int lane = gtid & 31;
    if (e >= E) return;

    int sN = __ldg(src + e);
    int dN = __ldg(dst + e);

    // Each lane covers 4 contiguous floats; lanes 0..7 -> head 0, etc.
    float4 qv = *(const float4*)(q + (size_t)dN * HID + lane * 4);
    float4 kv = *(const float4*)(kb + (size_t)sN * HID + lane * 4);
    float p = qv.x * kv.x + qv.y * kv.y + qv.z * kv.z + qv.w * kv.w;
    p += __shfl_xor_sync(0xffffffffu, p, 1);
    p += __shfl_xor_sync(0xffffffffu, p, 2);
    p += __shfl_xor_sync(0xffffffffu, p, 4);   // per-head dot product (8 lanes)

    int h = lane >> 3;
    float score = p * __ldg(pri + h) * 0.17677669529663689f;  // 1/sqrt(32)
    float ee = __expf(score);

    if ((lane & 7) == 0) atomicAdd(z + (size_t)dN * NH + h, ee);

    float4 vv = *(const float4*)(vb + (size_t)sN * HID + lane * 4);
    float* aptr = agg + (size_t)dN * HID + lane * 4;
    asm volatile("red.global.add.v4.f32 [%0], {%1,%2,%3,%4};"
                 :: "l"(aptr), "f"(ee * vv.x), "f"(ee * vv.y),
                    "f"(ee * vv.z), "f"(ee * vv.w)
                 : "memory");
}

// ---------------------------------------------------------------------------
// Combine: per-relation softmax normalization + cross-relation mean.
// type0 <- r1 only; type1 <- mean(r0, r2). Guards empty segments (z == 0).
// ---------------------------------------------------------------------------
__global__ void combine_kernel(int n) {
    int i = blockIdx.x * blockDim.x + threadIdx.x;
    if (i >= n) return;
    int node = i >> 7;
    int h = (i >> 5) & 3;

    float z1 = g_z[1][node * NH + h];
    float inv1 = (z1 > 0.f) ? 1.f / z1 : 0.f;
    g_tm[0][i] = g_agg[1][i] * inv1;

    float z0 = g_z[0][node * NH + h];
    float inv0 = (z0 > 0.f) ? 1.f / z0 : 0.f;
    float z2 = g_z[2][node * NH + h];
    float inv2 = (z2 > 0.f) ? 1.f / z2 : 0.f;
    g_tm[1][i] = 0.5f * (g_agg[0][i] * inv0 + g_agg[2][i] * inv2);
}

// ---------------------------------------------------------------------------
// Launch
// ---------------------------------------------------------------------------
extern "C" void kernel_launch(void* const* d_in, const int* in_sizes, int n_in,
                              void* d_out, int out_size) {
    const float* h0      = (const float*)d_in[0];
    const float* h1      = (const float*)d_in[1];
    const float* Wk      = (const float*)d_in[2];
    const float* bk      = (const float*)d_in[3];
    const float* Wq      = (const float*)d_in[4];
    const float* bq      = (const float*)d_in[5];
    const float* Wv      = (const float*)d_in[6];
    const float* bv      = (const float*)d_in[7];
    const float* Wa      = (const float*)d_in[8];
    const float* ba      = (const float*)d_in[9];
    const float* rel_att = (const float*)d_in[10];
    const float* rel_msg = (const float*)d_in[11];
    const float* rel_pri = (const float*)d_in[12];
    const float* skip    = (const float*)d_in[13];
    const int*   src0    = (const int*)d_in[14];
    const int*   dst0    = (const int*)d_in[15];
    const int*   src1    = (const int*)d_in[16];
    const int*   dst1    = (const int*)d_in[17];
    const int*   src2    = (const int*)d_in[18];
    const int*   dst2    = (const int*)d_in[19];

    int M  = in_sizes[0] / HID;     // 50000
    int E0 = in_sizes[14];
    int E1 = in_sizes[16];
    int E2 = in_sizes[18];
    float* out = (float*)d_out;

    // Resolve device-global addresses
    float *qbuf, *kbuf, *vbuf, *zbuf, *aggbuf, *tmbuf, *Wcbuf, *bcbuf;
    cudaGetSymbolAddress((void**)&qbuf,   g_q);
    cudaGetSymbolAddress((void**)&kbuf,   g_k);
    cudaGetSymbolAddress((void**)&vbuf,   g_v);
    cudaGetSymbolAddress((void**)&zbuf,   g_z);
    cudaGetSymbolAddress((void**)&aggbuf, g_agg);
    cudaGetSymbolAddress((void**)&tmbuf,  g_tm);
    cudaGetSymbolAddress((void**)&Wcbuf,  g_Wc);
    cudaGetSymbolAddress((void**)&bcbuf,  g_bc);

    float* q0 = qbuf;               float* q1 = qbuf + (size_t)NNODES * HID;
    float* k0 = kbuf;               float* k1 = kbuf + (size_t)NNODES * HID;
    float* k2 = kbuf + 2 * (size_t)NNODES * HID;
    float* v0 = vbuf;               float* v1 = vbuf + (size_t)NNODES * HID;
    float* v2 = vbuf + 2 * (size_t)NNODES * HID;
    float* z0 = zbuf;               float* z1 = zbuf + (size_t)NNODES * NH;
    float* z2 = zbuf + 2 * (size_t)NNODES * NH;
    float* a0 = aggbuf;             float* a1 = aggbuf + (size_t)NNODES * HID;
    float* a2 = aggbuf + 2 * (size_t)NNODES * HID;
    float* tm0 = tmbuf;             float* tm1 = tmbuf + (size_t)NNODES * HID;

    // Zero accumulators (agg: 3*M*128 floats, z: 3*M*4 floats)
    {
        int n4 = (3 * M * HID) / 4;
        zero_kernel<<<(n4 + 255) / 256, 256>>>(aggbuf, n4);
        int n4z = (3 * M * NH) / 4;
        zero_kernel<<<(n4z + 255) / 256, 256>>>(zbuf, n4z);
    }

    // Fold rel_att/rel_msg into the projection weights
    prep_comb<<<dim3(6, 129), 128>>>(Wk, bk, Wv, bv, rel_att, rel_msg);

    int gblocks = (M + 127) / 128;
    // q projections (per node type)
    gemm_fused<<<gblocks, 256>>>(h0, Wq,             bq,       q0, M, nullptr, nullptr);
    gemm_fused<<<gblocks, 256>>>(h1, Wq + HID * HID, bq + HID, q1, M, nullptr, nullptr);
    // folded k'/v' per relation (src types: r0<-h0, r1<-h1, r2<-h1)
    gemm_fused<<<gblocks, 256>>>(h0, Wcbuf + 0 * HID * HID, bcbuf + 0 * HID, k0, M, nullptr, nullptr);
    gemm_fused<<<gblocks, 256>>>(h0, Wcbuf + 1 * HID * HID, bcbuf + 1 * HID, v0, M, nullptr, nullptr);
    gemm_fused<<<gblocks, 256>>>(h1, Wcbuf + 2 * HID * HID, bcbuf + 2 * HID, k1, M, nullptr, nullptr);
    gemm_fused<<<gblocks, 256>>>(h1, Wcbuf + 3 * HID * HID, bcbuf + 3 * HID, v1, M, nullptr, nullptr);
    gemm_fused<<<gblocks, 256>>>(h1, Wcbuf + 4 * HID * HID, bcbuf + 4 * HID, k2, M, nullptr, nullptr);
    gemm_fused<<<gblocks, 256>>>(h1, Wcbuf + 5 * HID * HID, bcbuf + 5 * HID, v2, M, nullptr, nullptr);

    // Edge passes: q comes from the DESTINATION type (r0->q1, r1->q0, r2->q1)
    edge_kernel<<<(E0 * 32 + 255) / 256, 256>>>(src0, dst0, E0, q1, k0, v0, rel_pri + 0 * NH, z0, a0);
    edge_kernel<<<(E1 * 32 + 255) / 256, 256>>>(src1, dst1, E1, q0, k1, v1, rel_pri + 1 * NH, z1, a1);
    edge_kernel<<<(E2 * 32 + 255) / 256, 256>>>(src2, dst2, E2, q1, k2, v2, rel_pri + 2 * NH, z2, a2);

    // Normalize + cross-relation mean
    {
        int n = M * HID;
        combine_kernel<<<(n + 255) / 256, 256>>>(n);
    }

    // Output GEMMs with skip blend: out[t] = (tm@Wa[t]+ba[t])*sig(skip[t]) + h[t]*(1-sig)
    gemm_fused<<<gblocks, 256>>>(tm0, Wa,             ba,       out,                   M, skip + 0, h0);
    gemm_fused<<<gblocks, 256>>>(tm1, Wa + HID * HID, ba + HID, out + (size_t)M * HID, M, skip + 1, h1);
}

// round 3
// speedup vs baseline: 1.3550x; 1.3550x over previous
#include <cuda_runtime.h>
#include <cuda_bf16.h>
#include <cstdint>
#include <math.h>

// Problem constants (fixed by the dataset)
#define NNODES 50000
#define HID 128
#define NH 4
#define DKH 32

#define AROW 136                      // padded row stride (elems) => 272B
#define IMG_ELEMS (HID * AROW)        // 17408 elems per weight image
#define IMG_BYTES (IMG_ELEMS * 2)     // 34816 B

// ---------------------------------------------------------------------------
// Scratch: __device__ globals (no allocation allowed in kernel_launch)
// ---------------------------------------------------------------------------
__device__ float g_q[2][NNODES * HID];
__device__ float g_k[3][NNODES * HID];
__device__ float g_v[3][NNODES * HID];
__device__ float g_z[3][NNODES * NH];
__device__ float g_agg[3][NNODES * HID];
__device__ float g_tm[2][NNODES * HID];
__device__ float g_Wc[6][HID * HID];
__device__ float g_bc[6][HID];
// Transposed (B^T = [n][k]) padded bf16 hi/lo weight images
__device__ __nv_bfloat16 g_Wimg[10][2][IMG_ELEMS];

// ---------------------------------------------------------------------------
// PTX helpers: ldmatrix + mma.sync (plain sm_80+ instructions, no 'a' suffix)
// ---------------------------------------------------------------------------
__device__ __forceinline__ uint32_t smem_u32(const void* p) {
    uint32_t a;
    asm("{ .reg .u64 t; cvta.to.shared.u64 t, %1; cvt.u32.u64 %0, t; }"
        : "=r"(a) : "l"(p));
    return a;
}

__device__ __forceinline__ void ldsm_x4(uint32_t* r, uint32_t addr) {
    asm volatile("ldmatrix.sync.aligned.m8n8.x4.shared.b16 {%0,%1,%2,%3}, [%4];"
                 : "=r"(r[0]), "=r"(r[1]), "=r"(r[2]), "=r"(r[3]) : "r"(addr));
}
__device__ __forceinline__ void ldsm_x2(uint32_t* r, uint32_t addr) {
    asm volatile("ldmatrix.sync.aligned.m8n8.x2.shared.b16 {%0,%1}, [%2];"
                 : "=r"(r[0]), "=r"(r[1]) : "r"(addr));
}
__device__ __forceinline__ void mma16816(float* d, const uint32_t* a, const uint32_t* b) {
    asm volatile(
        "mma.sync.aligned.m16n8k16.row.col.f32.bf16.bf16.f32 "
        "{%0,%1,%2,%3}, {%4,%5,%6,%7}, {%8,%9}, {%0,%1,%2,%3};"
        : "+f"(d[0]), "+f"(d[1]), "+f"(d[2]), "+f"(d[3])
        : "r"(a[0]), "r"(a[1]), "r"(a[2]), "r"(a[3]), "r"(b[0]), "r"(b[1]));
}

// ---------------------------------------------------------------------------
// Zero a float buffer
// ---------------------------------------------------------------------------
__global__ void zero_kernel(float* __restrict__ p, int n4) {
    int i = blockIdx.x * blockDim.x + threadIdx.x;
    int stride = gridDim.x * blockDim.x;
    float4 zz = make_float4(0.f, 0.f, 0.f, 0.f);
    for (; i < n4; i += stride) ((float4*)p)[i] = zz;
}

// ---------------------------------------------------------------------------
// Wc[m] = Wbase[s] @ blockdiag_h(rel[r,h]); blockIdx.y == 128 -> bias row
// ---------------------------------------------------------------------------
__global__ void prep_comb(const float* __restrict__ Wk, const float* __restrict__ bk,
                          const float* __restrict__ Wv, const float* __restrict__ bv,
                          const float* __restrict__ rel_att, const float* __restrict__ rel_msg) {
    int m = blockIdx.x;
    int r = m >> 1;
    int kind = m & 1;
    int s = (r == 0) ? 0 : 1;
    const float* Wbase = kind ? Wv : Wk;
    const float* bbase = kind ? bv : bk;
    const float* rel   = kind ? rel_msg : rel_att;

    int c = blockIdx.y;
    int j = threadIdx.x;
    int h = j >> 5;
    int jj = j & 31;
    const float* A = rel + ((size_t)r * NH + h) * DKH * DKH;

    float sum = 0.f;
    if (c < HID) {
        const float* wrow = Wbase + (size_t)s * HID * HID + (size_t)c * HID + h * DKH;
        #pragma unroll
        for (int i = 0; i < DKH; i++) sum = fmaf(wrow[i], A[i * DKH + jj], sum);
        g_Wc[m][c * HID + j] = sum;
    } else {
        const float* brow = bbase + s * HID + h * DKH;
        #pragma unroll
        for (int i = 0; i < DKH; i++) sum = fmaf(brow[i], A[i * DKH + jj], sum);
        g_bc[m][j] = sum;
    }
}

// ---------------------------------------------------------------------------
// Build transposed padded bf16 hi/lo weight images: img[n*AROW + k] = W[k][n]
// ---------------------------------------------------------------------------
__global__ void convertW(const float* __restrict__ Wq, const float* __restrict__ Wa) {
    int idx = blockIdx.x * blockDim.x + threadIdx.x;
    if (idx >= 10 * HID * HID) return;
    int m = idx >> 14;
    int rem = idx & 16383;
    int n = rem >> 7;
    int k = rem & 127;

    const float* src;
    if (m < 6)       src = g_Wc[m];
    else if (m == 6) src = Wq;
    else if (m == 7) src = Wq + HID * HID;
    else if (m == 8) src = Wa;
    else             src = Wa + HID * HID;

    float w = src[k * HID + n];
    __nv_bfloat16 hi = __float2bfloat16(w);
    __nv_bfloat16 lo = __float2bfloat16(w - __bfloat162float(hi));
    g_Wimg[m][0][n * AROW + k] = hi;
    g_Wimg[m][1][n * AROW + k] = lo;
}

// ---------------------------------------------------------------------------
// Batched tensor-core GEMM: for each set s, C_s = A @ W_s + bias_s
// (optional skip-blend). A[M,128] loaded & split into bf16 hi/lo smem ONCE.
// bf16x3: D = Ahi*Bhi + Ahi*Blo + Alo*Bhi (fp32 accum in registers).
// 256 threads, 8 warps (4x2), warp tile 32x64, mma m16n8k16.
// ---------------------------------------------------------------------------
struct GemmSet {
    const __nv_bfloat16* whi;
    const __nv_bfloat16* wlo;
    const float* bias;
    float* C;
};
struct GemmBatch {
    GemmSet s[5];
    int nsets;
    const float* skipv;   // nullptr unless skip-blend
    const float* res;
};

#define OFF_AHI 0
#define OFF_ALO IMG_BYTES
#define OFF_BHI (2 * IMG_BYTES)
#define OFF_BLO (3 * IMG_BYTES)
#define SMEM_TOT (4 * IMG_BYTES)      // 139264 B

__global__ __launch_bounds__(256) void gemm_mma(
    const float* __restrict__ A, GemmBatch batch, int M) {
    extern __shared__ char smem[];
    uint32_t sbase = smem_u32(smem);
    int tid = threadIdx.x;
    int wid = tid >> 5;
    int lane = tid & 31;
    int wr = wid >> 1;            // warp row 0..3 (32 rows each)
    int wc = wid & 1;             // warp col 0..1 (64 cols each)
    int row0 = blockIdx.x * 128;

    // ---- Load A tile, split into bf16 hi/lo, store padded row-major ----
    for (int i = tid; i < 128 * 64; i += 256) {
        int r = i >> 6;
        int c = (i & 63) * 2;
        int grow = row0 + r;
        float2 v = make_float2(0.f, 0.f);
        if (grow < M) v = *(const float2*)(A + (size_t)grow * HID + c);
        __nv_bfloat16 h0 = __float2bfloat16(v.x);
        __nv_bfloat16 h1 = __float2bfloat16(v.y);
        __nv_bfloat16 l0 = __float2bfloat16(v.x - __bfloat162float(h0));
        __nv_bfloat16 l1 = __float2bfloat16(v.y - __bfloat162float(h1));
        __nv_bfloat162 hp; hp.x = h0; hp.y = h1;
        __nv_bfloat162 lp; lp.x = l0; lp.y = l1;
        uint32_t off = (uint32_t)(r * (AROW * 2) + c * 2);
        *(__nv_bfloat162*)(smem + OFF_AHI + off) = hp;
        *(__nv_bfloat162*)(smem + OFF_ALO + off) = lp;
    }

    // Precompute per-thread ldmatrix byte offsets (within a tile image)
    // A x4: row = wr*32 + mt*16 + ((lane>>3)&1)*8 + (lane&7); col = kt*16 + (lane>>4)*8
    uint32_t a_row = (uint32_t)(wr * 32 + ((lane >> 3) & 1) * 8 + (lane & 7));
    uint32_t a_col8 = (uint32_t)((lane >> 4) * 8);
    // B x2: l = lane&15: row n = wc*64 + nt*8 + (l&7); col = kt*16 + (l>>3)*8
    int bl = lane & 15;
    uint32_t b_row = (uint32_t)(wc * 64 + (bl & 7));
    uint32_t b_col8 = (uint32_t)((bl >> 3) * 8);

    float alpha = 1.f, beta = 0.f;
    if (batch.skipv) {
        float sv = *batch.skipv;
        alpha = 1.f / (1.f + expf(-sv));
        beta = 1.f - alpha;
    }

    for (int s = 0; s < batch.nsets; s++) {
        // ---- Copy pre-built W images into smem (byte copy, incl. pad) ----
        __syncthreads();   // previous set's ldmatrix reads done before overwrite
        {
            const uint4* wh = (const uint4*)batch.s[s].whi;
            const uint4* wl = (const uint4*)batch.s[s].wlo;
            uint4* sh = (uint4*)(smem + OFF_BHI);
            uint4* sl = (uint4*)(smem + OFF_BLO);
            for (int i = tid; i < IMG_BYTES / 16; i += 256) {
                sh[i] = wh[i];
                sl[i] = wl[i];
            }
        }
        __syncthreads();

        float acc[2][8][4];
        #pragma unroll
        for (int mt = 0; mt < 2; mt++)
            #pragma unroll
            for (int nt = 0; nt < 8; nt++)
                #pragma unroll
                for (int u = 0; u < 4; u++) acc[mt][nt][u] = 0.f;

        #pragma unroll
        for (int kt = 0; kt < 8; kt++) {
            uint32_t kcol = (uint32_t)(kt * 16);
            uint32_t ah[2][4], al[2][4];
            #pragma unroll
            for (int mt = 0; mt < 2; mt++) {
                uint32_t aoff = (a_row + mt * 16) * (AROW * 2) + (kcol + a_col8) * 2;
                ldsm_x4(ah[mt], sbase + OFF_AHI + aoff);
                ldsm_x4(al[mt], sbase + OFF_ALO + aoff);
            }
            #pragma unroll
            for (int nt = 0; nt < 8; nt++) {
                uint32_t boff = (b_row + nt * 8) * (AROW * 2) + (kcol + b_col8) * 2;
                uint32_t bh[2], blr[2];
                ldsm_x2(bh, sbase + OFF_BHI + boff);
                ldsm_x2(blr, sbase + OFF_BLO + boff);
                #pragma unroll
                for (int mt = 0; mt < 2; mt++) {
                    mma16816(acc[mt][nt], ah[mt], bh);
                    mma16816(acc[mt][nt], ah[mt], blr);
                    mma16816(acc[mt][nt], al[mt], bh);
                }
            }
        }

        // ---- Epilogue ----
        const float* bias = batch.s[s].bias;
        float* C = batch.s[s].C;
        const float* res = batch.res;
        #pragma unroll
        for (int mt = 0; mt < 2; mt++) {
            int row_base = row0 + wr * 32 + mt * 16 + (lane >> 2);
            #pragma unroll
            for (int half = 0; half < 2; half++) {
                int row = row_base + half * 8;
                if (row >= M) continue;
                #pragma unroll
                for (int nt = 0; nt < 8; nt++) {
                    int col = wc * 64 + nt * 8 + (lane & 3) * 2;
                    float2 o;
                    o.x = acc[mt][nt][half * 2 + 0] + bias[col];
                    o.y = acc[mt][nt][half * 2 + 1] + bias[col + 1];
                    if (res) {
                        float2 rv = *(const float2*)(res + (size_t)row * HID + col);
                        o.x = o.x * alpha + rv.x * beta;
                        o.y = o.y * alpha + rv.y * beta;
                    }
                    *(float2*)(C + (size_t)row * HID + col) = o;
                }
            }
        }
    }
}

// ---------------------------------------------------------------------------
// Edge kernel: one warp per edge (unchanged from R1 pass).
// ---------------------------------------------------------------------------
__global__ __launch_bounds__(256) void edge_kernel(
    const int* __restrict__ src, const int* __restrict__ dst, int E,
    const float* __restrict__ q, const float* __restrict__ kb,
    const float* __restrict__ vb, const float* __restrict__ pri,
    float* __restrict__ z, float* __restrict__ agg) {
    int gtid = blockIdx.x * blockDim.x + threadIdx.x;
    int e = gtid >> 5;
    int lane = gtid & 31;
    if (e >= E) return;

    int sN = __ldg(src + e);
    int dN = __ldg(dst + e);

    float4 qv = *(const float4*)(q + (size_t)dN * HID + lane * 4);
    float4 kv = *(const float4*)(kb + (size_t)sN * HID + lane * 4);
    float p = qv.x * kv.x + qv.y * kv.y + qv.z * kv.z + qv.w * kv.w;
    p += __shfl_xor_sync(0xffffffffu, p, 1);
    p += __shfl_xor_sync(0xffffffffu, p, 2);
    p += __shfl_xor_sync(0xffffffffu, p, 4);

    int h = lane >> 3;
    float score = p * __ldg(pri + h) * 0.17677669529663689f;
    float ee = __expf(score);

    if ((lane & 7) == 0) atomicAdd(z + (size_t)dN * NH + h, ee);

    float4 vv = *(const float4*)(vb + (size_t)sN * HID + lane * 4);
    float* aptr = agg + (size_t)dN * HID + lane * 4;
    asm volatile("red.global.add.v4.f32 [%0], {%1,%2,%3,%4};"
                 :: "l"(aptr), "f"(ee * vv.x), "f"(ee * vv.y),
                    "f"(ee * vv.z), "f"(ee * vv.w)
                 : "memory");
}

// ---------------------------------------------------------------------------
// Combine: per-relation softmax normalization + cross-relation mean.
// ---------------------------------------------------------------------------
__global__ void combine_kernel(int n) {
    int i = blockIdx.x * blockDim.x + threadIdx.x;
    if (i >= n) return;
    int node = i >> 7;
    int h = (i >> 5) & 3;

    float z1 = g_z[1][node * NH + h];
    float inv1 = (z1 > 0.f) ? 1.f / z1 : 0.f;
    g_tm[0][i] = g_agg[1][i] * inv1;

    float z0 = g_z[0][node * NH + h];
    float inv0 = (z0 > 0.f) ? 1.f / z0 : 0.f;
    float z2 = g_z[2][node * NH + h];
    float inv2 = (z2 > 0.f) ? 1.f / z2 : 0.f;
    g_tm[1][i] = 0.5f * (g_agg[0][i] * inv0 + g_agg[2][i] * inv2);
}

// ---------------------------------------------------------------------------
// Launch
// ---------------------------------------------------------------------------
extern "C" void kernel_launch(void* const* d_in, const int* in_sizes, int n_in,
                              void* d_out, int out_size) {
    const float* h0      = (const float*)d_in[0];
    const float* h1      = (const float*)d_in[1];
    const float* Wk      = (const float*)d_in[2];
    const float* bk      = (const float*)d_in[3];
    const float* Wq      = (const float*)d_in[4];
    const float* bq      = (const float*)d_in[5];
    const float* Wv      = (const float*)d_in[6];
    const float* bv      = (const float*)d_in[7];
    const float* Wa      = (const float*)d_in[8];
    const float* ba      = (const float*)d_in[9];
    const float* rel_att = (const float*)d_in[10];
    const float* rel_msg = (const float*)d_in[11];
    const float* rel_pri = (const float*)d_in[12];
    const float* skip    = (const float*)d_in[13];
    const int*   src0    = (const int*)d_in[14];
    const int*   dst0    = (const int*)d_in[15];
    const int*   src1    = (const int*)d_in[16];
    const int*   dst1    = (const int*)d_in[17];
    const int*   src2    = (const int*)d_in[18];
    const int*   dst2    = (const int*)d_in[19];

    int M  = in_sizes[0] / HID;
    int E0 = in_sizes[14];
    int E1 = in_sizes[16];
    int E2 = in_sizes[18];
    float* out = (float*)d_out;

    cudaFuncSetAttribute(gemm_mma, cudaFuncAttributeMaxDynamicSharedMemorySize, SMEM_TOT);

    float *qbuf, *kbuf, *vbuf, *zbuf, *aggbuf, *tmbuf, *bcbuf;
    __nv_bfloat16* wimg;
    cudaGetSymbolAddress((void**)&qbuf,   g_q);
    cudaGetSymbolAddress((void**)&kbuf,   g_k);
    cudaGetSymbolAddress((void**)&vbuf,   g_v);
    cudaGetSymbolAddress((void**)&zbuf,   g_z);
    cudaGetSymbolAddress((void**)&aggbuf, g_agg);
    cudaGetSymbolAddress((void**)&tmbuf,  g_tm);
    cudaGetSymbolAddress((void**)&bcbuf,  g_bc);
    cudaGetSymbolAddress((void**)&wimg,   g_Wimg);

    float* q0 = qbuf;               float* q1 = qbuf + (size_t)NNODES * HID;
    float* k0 = kbuf;               float* k1 = kbuf + (size_t)NNODES * HID;
    float* k2 = kbuf + 2 * (size_t)NNODES * HID;
    float* v0 = vbuf;               float* v1 = vbuf + (size_t)NNODES * HID;
    float* v2 = vbuf + 2 * (size_t)NNODES * HID;
    float* z0 = zbuf;               float* z1 = zbuf + (size_t)NNODES * NH;
    float* z2 = zbuf + 2 * (size_t)NNODES * NH;
    float* a0 = aggbuf;             float* a1 = aggbuf + (size_t)NNODES * HID;
    float* a2 = aggbuf + 2 * (size_t)NNODES * HID;
    float* tm0 = tmbuf;             float* tm1 = tmbuf + (size_t)NNODES * HID;

    #define WIMG(m, hl) (wimg + ((size_t)(m) * 2 + (hl)) * IMG_ELEMS)

    // Zero accumulators
    {
        int n4 = (3 * M * HID) / 4;
        zero_kernel<<<(n4 + 255) / 256, 256>>>(aggbuf, n4);
        int n4z = (3 * M * NH) / 4;
        zero_kernel<<<(n4z + 255) / 256, 256>>>(zbuf, n4z);
    }

    // Fold rel matrices into weights, then build bf16 hi/lo transposed images
    prep_comb<<<dim3(6, 129), 128>>>(Wk, bk, Wv, bv, rel_att, rel_msg);
    convertW<<<(10 * HID * HID + 255) / 256, 256>>>(Wq, Wa);

    int gb = (M + 127) / 128;

    // Batched projection GEMMs (A shared within batch)
    {
        GemmBatch b0 = {};
        b0.nsets = 3;
        b0.s[0] = { WIMG(6,0), WIMG(6,1), bq,             q0 };
        b0.s[1] = { WIMG(0,0), WIMG(0,1), bcbuf + 0*HID,  k0 };
        b0.s[2] = { WIMG(1,0), WIMG(1,1), bcbuf + 1*HID,  v0 };
        b0.skipv = nullptr; b0.res = nullptr;
        gemm_mma<<<gb, 256, SMEM_TOT>>>(h0, b0, M);

        GemmBatch b1 = {};
        b1.nsets = 5;
        b1.s[0] = { WIMG(7,0), WIMG(7,1), bq + HID,       q1 };
        b1.s[1] = { WIMG(2,0), WIMG(2,1), bcbuf + 2*HID,  k1 };
        b1.s[2] = { WIMG(3,0), WIMG(3,1), bcbuf + 3*HID,  v1 };
        b1.s[3] = { WIMG(4,0), WIMG(4,1), bcbuf + 4*HID,  k2 };
        b1.s[4] = { WIMG(5,0), WIMG(5,1), bcbuf + 5*HID,  v2 };
        b1.skipv = nullptr; b1.res = nullptr;
        gemm_mma<<<gb, 256, SMEM_TOT>>>(h1, b1, M);
    }

    // Edge passes (q from destination type: r0->q1, r1->q0, r2->q1)
    edge_kernel<<<(E0 * 32 + 255) / 256, 256>>>(src0, dst0, E0, q1, k0, v0, rel_pri + 0 * NH, z0, a0);
    edge_kernel<<<(E1 * 32 + 255) / 256, 256>>>(src1, dst1, E1, q0, k1, v1, rel_pri + 1 * NH, z1, a1);
    edge_kernel<<<(E2 * 32 + 255) / 256, 256>>>(src2, dst2, E2, q1, k2, v2, rel_pri + 2 * NH, z2, a2);

    // Normalize + cross-relation mean
    {
        int n = M * HID;
        combine_kernel<<<(n + 255) / 256, 256>>>(n);
    }

    // Output GEMMs with skip blend
    {
        GemmBatch o0 = {};
        o0.nsets = 1;
        o0.s[0] = { WIMG(8,0), WIMG(8,1), ba,       out };
        o0.skipv = skip + 0; o0.res = h0;
        gemm_mma<<<gb, 256, SMEM_TOT>>>(tm0, o0, M);

        GemmBatch o1 = {};
        o1.nsets = 1;
        o1.s[0] = { WIMG(9,0), WIMG(9,1), ba + HID, out + (size_t)M * HID };
        o1.skipv = skip + 1; o1.res = h1;
        gemm_mma<<<gb, 256, SMEM_TOT>>>(tm1, o1, M);
    }
}

// round 4
// speedup vs baseline: 1.3693x; 1.0106x over previous
#include <cuda_runtime.h>
#include <cuda_bf16.h>
#include <cstdint>
#include <math.h>

// Problem constants (fixed by the dataset)
#define NNODES 50000
#define HID 128
#define NH 4
#define DKH 32
#define EMAX 400000

#define AROW 136                      // padded row stride (elems) => 272B
#define IMG_ELEMS (HID * AROW)        // 17408 elems per weight image
#define IMG_BYTES (IMG_ELEMS * 2)     // 34816 B

// ---------------------------------------------------------------------------
// Scratch: __device__ globals
// ---------------------------------------------------------------------------
__device__ float g_q[2][NNODES * HID];
__device__ float g_k[3][NNODES * HID];
__device__ float g_v[3][NNODES * HID];
__device__ float g_t0[NNODES * HID];        // normalized agg of relation 0 (tmp)
__device__ float g_tm[2][NNODES * HID];     // GEMM inputs for output stage
__device__ float g_Wc[6][HID * HID];
__device__ float g_bc[6][HID];
__device__ __nv_bfloat16 g_Wimg[10][2][IMG_ELEMS];
// CSR build scratch
__device__ int g_hist[3][NNODES];
__device__ int g_off[3][NNODES + 1];
__device__ int g_cur[3][NNODES];
__device__ int g_esrc[3][EMAX];

// ---------------------------------------------------------------------------
// PTX helpers: ldmatrix + mma.sync (plain sm_80+ instructions)
// ---------------------------------------------------------------------------
__device__ __forceinline__ uint32_t smem_u32(const void* p) {
    uint32_t a;
    asm("{ .reg .u64 t; cvta.to.shared.u64 t, %1; cvt.u32.u64 %0, t; }"
        : "=r"(a) : "l"(p));
    return a;
}
__device__ __forceinline__ void ldsm_x4(uint32_t* r, uint32_t addr) {
    asm volatile("ldmatrix.sync.aligned.m8n8.x4.shared.b16 {%0,%1,%2,%3}, [%4];"
                 : "=r"(r[0]), "=r"(r[1]), "=r"(r[2]), "=r"(r[3]) : "r"(addr));
}
__device__ __forceinline__ void ldsm_x2(uint32_t* r, uint32_t addr) {
    asm volatile("ldmatrix.sync.aligned.m8n8.x2.shared.b16 {%0,%1}, [%2];"
                 : "=r"(r[0]), "=r"(r[1]) : "r"(addr));
}
__device__ __forceinline__ void mma16816(float* d, const uint32_t* a, const uint32_t* b) {
    asm volatile(
        "mma.sync.aligned.m16n8k16.row.col.f32.bf16.bf16.f32 "
        "{%0,%1,%2,%3}, {%4,%5,%6,%7}, {%8,%9}, {%0,%1,%2,%3};"
        : "+f"(d[0]), "+f"(d[1]), "+f"(d[2]), "+f"(d[3])
        : "r"(a[0]), "r"(a[1]), "r"(a[2]), "r"(a[3]), "r"(b[0]), "r"(b[1]));
}

// ---------------------------------------------------------------------------
// Zero a buffer (float4 stores; also used for int arrays bitwise)
// ---------------------------------------------------------------------------
__global__ void zero_kernel(float* __restrict__ p, int n4) {
    int i = blockIdx.x * blockDim.x + threadIdx.x;
    int stride = gridDim.x * blockDim.x;
    float4 zz = make_float4(0.f, 0.f, 0.f, 0.f);
    for (; i < n4; i += stride) ((float4*)p)[i] = zz;
}

// ---------------------------------------------------------------------------
// CSR build: histogram -> scan -> scatter
// ---------------------------------------------------------------------------
__global__ void hist_kernel(const int* __restrict__ dst, int E, int r) {
    int i = blockIdx.x * blockDim.x + threadIdx.x;
    if (i < E) atomicAdd(&g_hist[r][dst[i]], 1);
}

__global__ __launch_bounds__(1024) void scan_kernel() {
    int r = blockIdx.x;
    int t = threadIdx.x;
    __shared__ int part[1024];
    const int CH = (NNODES + 1023) / 1024;   // 49
    int beg = t * CH;
    int end = beg + CH; if (end > NNODES) end = NNODES;
    if (beg > NNODES) beg = NNODES;
    int s = 0;
    for (int i = beg; i < end; i++) s += g_hist[r][i];
    part[t] = s;
    __syncthreads();
    for (int d = 1; d < 1024; d <<= 1) {
        int v = (t >= d) ? part[t - d] : 0;
        __syncthreads();
        part[t] += v;
        __syncthreads();
    }
    int run = (t == 0) ? 0 : part[t - 1];
    for (int i = beg; i < end; i++) {
        int c = g_hist[r][i];
        g_off[r][i] = run;
        g_cur[r][i] = run;
        run += c;
    }
    if (end == NNODES) g_off[r][NNODES] = run;
}

__global__ void scatter_kernel(const int* __restrict__ src, const int* __restrict__ dst,
                               int E, int r) {
    int i = blockIdx.x * blockDim.x + threadIdx.x;
    if (i < E) {
        int d = dst[i];
        int pos = atomicAdd(&g_cur[r][d], 1);
        g_esrc[r][pos] = src[i];
    }
}

// ---------------------------------------------------------------------------
// Wc[m] = Wbase[s] @ blockdiag_h(rel[r,h]); blockIdx.y == 128 -> bias row
// ---------------------------------------------------------------------------
__global__ void prep_comb(const float* __restrict__ Wk, const float* __restrict__ bk,
                          const float* __restrict__ Wv, const float* __restrict__ bv,
                          const float* __restrict__ rel_att, const float* __restrict__ rel_msg) {
    int m = blockIdx.x;
    int r = m >> 1;
    int kind = m & 1;
    int s = (r == 0) ? 0 : 1;
    const float* Wbase = kind ? Wv : Wk;
    const float* bbase = kind ? bv : bk;
    const float* rel   = kind ? rel_msg : rel_att;

    int c = blockIdx.y;
    int j = threadIdx.x;
    int h = j >> 5;
    int jj = j & 31;
    const float* A = rel + ((size_t)r * NH + h) * DKH * DKH;

    float sum = 0.f;
    if (c < HID) {
        const float* wrow = Wbase + (size_t)s * HID * HID + (size_t)c * HID + h * DKH;
        #pragma unroll
        for (int i = 0; i < DKH; i++) sum = fmaf(wrow[i], A[i * DKH + jj], sum);
        g_Wc[m][c * HID + j] = sum;
    } else {
        const float* brow = bbase + s * HID + h * DKH;
        #pragma unroll
        for (int i = 0; i < DKH; i++) sum = fmaf(brow[i], A[i * DKH + jj], sum);
        g_bc[m][j] = sum;
    }
}

// ---------------------------------------------------------------------------
// Build transposed padded bf16 hi/lo weight images: img[n*AROW + k] = W[k][n]
// ---------------------------------------------------------------------------
__global__ void convertW(const float* __restrict__ Wq, const float* __restrict__ Wa) {
    int idx = blockIdx.x * blockDim.x + threadIdx.x;
    if (idx >= 10 * HID * HID) return;
    int m = idx >> 14;
    int rem = idx & 16383;
    int n = rem >> 7;
    int k = rem & 127;

    const float* src;
    if (m < 6)       src = g_Wc[m];
    else if (m == 6) src = Wq;
    else if (m == 7) src = Wq + HID * HID;
    else if (m == 8) src = Wa;
    else             src = Wa + HID * HID;

    float w = src[k * HID + n];
    __nv_bfloat16 hi = __float2bfloat16(w);
    __nv_bfloat16 lo = __float2bfloat16(w - __bfloat162float(hi));
    g_Wimg[m][0][n * AROW + k] = hi;
    g_Wimg[m][1][n * AROW + k] = lo;
}

// ---------------------------------------------------------------------------
// Batched tensor-core GEMM (unchanged from R3, passed at rel_err 6e-6)
// ---------------------------------------------------------------------------
struct GemmSet {
    const __nv_bfloat16* whi;
    const __nv_bfloat16* wlo;
    const float* bias;
    float* C;
};
struct GemmBatch {
    GemmSet s[5];
    int nsets;
    const float* skipv;
    const float* res;
};

#define OFF_AHI 0
#define OFF_ALO IMG_BYTES
#define OFF_BHI (2 * IMG_BYTES)
#define OFF_BLO (3 * IMG_BYTES)
#define SMEM_TOT (4 * IMG_BYTES)

__global__ __launch_bounds__(256) void gemm_mma(
    const float* __restrict__ A, GemmBatch batch, int M) {
    extern __shared__ char smem[];
    uint32_t sbase = smem_u32(smem);
    int tid = threadIdx.x;
    int wid = tid >> 5;
    int lane = tid & 31;
    int wr = wid >> 1;
    int wc = wid & 1;
    int row0 = blockIdx.x * 128;

    for (int i = tid; i < 128 * 64; i += 256) {
        int r = i >> 6;
        int c = (i & 63) * 2;
        int grow = row0 + r;
        float2 v = make_float2(0.f, 0.f);
        if (grow < M) v = *(const float2*)(A + (size_t)grow * HID + c);
        __nv_bfloat16 h0 = __float2bfloat16(v.x);
        __nv_bfloat16 h1 = __float2bfloat16(v.y);
        __nv_bfloat16 l0 = __float2bfloat16(v.x - __bfloat162float(h0));
        __nv_bfloat16 l1 = __float2bfloat16(v.y - __bfloat162float(h1));
        __nv_bfloat162 hp; hp.x = h0; hp.y = h1;
        __nv_bfloat162 lp; lp.x = l0; lp.y = l1;
        uint32_t off = (uint32_t)(r * (AROW * 2) + c * 2);
        *(__nv_bfloat162*)(smem + OFF_AHI + off) = hp;
        *(__nv_bfloat162*)(smem + OFF_ALO + off) = lp;
    }

    uint32_t a_row = (uint32_t)(wr * 32 + ((lane >> 3) & 1) * 8 + (lane & 7));
    uint32_t a_col8 = (uint32_t)((lane >> 4) * 8);
    int bl = lane & 15;
    uint32_t b_row = (uint32_t)(wc * 64 + (bl & 7));
    uint32_t b_col8 = (uint32_t)((bl >> 3) * 8);

    float alpha = 1.f, beta = 0.f;
    if (batch.skipv) {
        float sv = *batch.skipv;
        alpha = 1.f / (1.f + expf(-sv));
        beta = 1.f - alpha;
    }

    for (int s = 0; s < batch.nsets; s++) {
        __syncthreads();
        {
            const uint4* wh = (const uint4*)batch.s[s].whi;
            const uint4* wl = (const uint4*)batch.s[s].wlo;
            uint4* sh = (uint4*)(smem + OFF_BHI);
            uint4* sl = (uint4*)(smem + OFF_BLO);
            for (int i = tid; i < IMG_BYTES / 16; i += 256) {
                sh[i] = wh[i];
                sl[i] = wl[i];
            }
        }
        __syncthreads();

        float acc[2][8][4];
        #pragma unroll
        for (int mt = 0; mt < 2; mt++)
            #pragma unroll
            for (int nt = 0; nt < 8; nt++)
                #pragma unroll
                for (int u = 0; u < 4; u++) acc[mt][nt][u] = 0.f;

        #pragma unroll
        for (int kt = 0; kt < 8; kt++) {
            uint32_t kcol = (uint32_t)(kt * 16);
            uint32_t ah[2][4], al[2][4];
            #pragma unroll
            for (int mt = 0; mt < 2; mt++) {
                uint32_t aoff = (a_row + mt * 16) * (AROW * 2) + (kcol + a_col8) * 2;
                ldsm_x4(ah[mt], sbase + OFF_AHI + aoff);
                ldsm_x4(al[mt], sbase + OFF_ALO + aoff);
            }
            #pragma unroll
            for (int nt = 0; nt < 8; nt++) {
                uint32_t boff = (b_row + nt * 8) * (AROW * 2) + (kcol + b_col8) * 2;
                uint32_t bh[2], blr[2];
                ldsm_x2(bh, sbase + OFF_BHI + boff);
                ldsm_x2(blr, sbase + OFF_BLO + boff);
                #pragma unroll
                for (int mt = 0; mt < 2; mt++) {
                    mma16816(acc[mt][nt], ah[mt], bh);
                    mma16816(acc[mt][nt], ah[mt], blr);
                    mma16816(acc[mt][nt], al[mt], bh);
                }
            }
        }

        const float* bias = batch.s[s].bias;
        float* C = batch.s[s].C;
        const float* res = batch.res;
        #pragma unroll
        for (int mt = 0; mt < 2; mt++) {
            int row_base = row0 + wr * 32 + mt * 16 + (lane >> 2);
            #pragma unroll
            for (int half = 0; half < 2; half++) {
                int row = row_base + half * 8;
                if (row >= M) continue;
                #pragma unroll
                for (int nt = 0; nt < 8; nt++) {
                    int col = wc * 64 + nt * 8 + (lane & 3) * 2;
                    float2 o;
                    o.x = acc[mt][nt][half * 2 + 0] + bias[col];
                    o.y = acc[mt][nt][half * 2 + 1] + bias[col + 1];
                    if (res) {
                        float2 rv = *(const float2*)(res + (size_t)row * HID + col);
                        o.x = o.x * alpha + rv.x * beta;
                        o.y = o.y * alpha + rv.y * beta;
                    }
                    *(float2*)(C + (size_t)row * HID + col) = o;
                }
            }
        }
    }
}

// ---------------------------------------------------------------------------
// Aggregation: one warp per destination node, CSR in-edge list.
// Softmax over in-edges computed locally (no atomics), normalized write.
// out = (acc/z + partner) * wmul   (partner=null -> own only)
// ---------------------------------------------------------------------------
__global__ __launch_bounds__(256) void agg_kernel(
    int rr, const float* __restrict__ q, const float* __restrict__ kb,
    const float* __restrict__ vb, const float* __restrict__ pri,
    float* __restrict__ out, const float* __restrict__ partner, float wmul) {
    int node = blockIdx.x * 8 + (threadIdx.x >> 5);
    int lane = threadIdx.x & 31;
    if (node >= NNODES) return;

    int off = g_off[rr][node];
    int deg = g_off[rr][node + 1] - off;
    const int* srcs = g_esrc[rr];

    float4 qv = *(const float4*)(q + (size_t)node * HID + lane * 4);
    int h = lane >> 3;
    float pr = __ldg(pri + h) * 0.17677669529663689f;   // pri[h] / sqrt(32)

    float4 acc = make_float4(0.f, 0.f, 0.f, 0.f);
    float zacc = 0.f;

    for (int b = 0; b < deg; b += 32) {
        int cnt = deg - b; if (cnt > 32) cnt = 32;
        int myid = (lane < cnt) ? __ldg(srcs + off + b + lane) : 0;

        int s0 = __shfl_sync(0xffffffffu, myid, 0);
        float4 kv = *(const float4*)(kb + (size_t)s0 * HID + lane * 4);
        float4 vv = *(const float4*)(vb + (size_t)s0 * HID + lane * 4);

        for (int t = 0; t < cnt; t++) {
            // prefetch next edge's k/v while computing current
            int sn = __shfl_sync(0xffffffffu, myid, (t + 1) & 31);
            float4 kn = make_float4(0.f, 0.f, 0.f, 0.f);
            float4 vn = kn;
            if (t + 1 < cnt) {
                kn = *(const float4*)(kb + (size_t)sn * HID + lane * 4);
                vn = *(const float4*)(vb + (size_t)sn * HID + lane * 4);
            }
            float p = qv.x * kv.x + qv.y * kv.y + qv.z * kv.z + qv.w * kv.w;
            p += __shfl_xor_sync(0xffffffffu, p, 1);
            p += __shfl_xor_sync(0xffffffffu, p, 2);
            p += __shfl_xor_sync(0xffffffffu, p, 4);   // per-head dot (8 lanes)
            float e = __expf(p * pr);
            zacc += e;
            acc.x = fmaf(e, vv.x, acc.x);
            acc.y = fmaf(e, vv.y, acc.y);
            acc.z = fmaf(e, vv.z, acc.z);
            acc.w = fmaf(e, vv.w, acc.w);
            kv = kn; vv = vn;
        }
    }

    float inv = (zacc > 0.f) ? 1.f / zacc : 0.f;   // zacc identical across head's 8 lanes
    float4 res;
    res.x = acc.x * inv; res.y = acc.y * inv;
    res.z = acc.z * inv; res.w = acc.w * inv;
    if (partner) {
        float4 pv = *(const float4*)(partner + (size_t)node * HID + lane * 4);
        res.x = (res.x + pv.x) * wmul;
        res.y = (res.y + pv.y) * wmul;
        res.z = (res.z + pv.z) * wmul;
        res.w = (res.w + pv.w) * wmul;
    }
    *(float4*)(out + (size_t)node * HID + lane * 4) = res;
}

// ---------------------------------------------------------------------------
// Launch
// ---------------------------------------------------------------------------
extern "C" void kernel_launch(void* const* d_in, const int* in_sizes, int n_in,
                              void* d_out, int out_size) {
    const float* h0      = (const float*)d_in[0];
    const float* h1      = (const float*)d_in[1];
    const float* Wk      = (const float*)d_in[2];
    const float* bk      = (const float*)d_in[3];
    const float* Wq      = (const float*)d_in[4];
    const float* bq      = (const float*)d_in[5];
    const float* Wv      = (const float*)d_in[6];
    const float* bv      = (const float*)d_in[7];
    const float* Wa      = (const float*)d_in[8];
    const float* ba      = (const float*)d_in[9];
    const float* rel_att = (const float*)d_in[10];
    const float* rel_msg = (const float*)d_in[11];
    const float* rel_pri = (const float*)d_in[12];
    const float* skip    = (const float*)d_in[13];
    const int*   src0    = (const int*)d_in[14];
    const int*   dst0    = (const int*)d_in[15];
    const int*   src1    = (const int*)d_in[16];
    const int*   dst1    = (const int*)d_in[17];
    const int*   src2    = (const int*)d_in[18];
    const int*   dst2    = (const int*)d_in[19];

    int M  = in_sizes[0] / HID;
    int E0 = in_sizes[14];
    int E1 = in_sizes[16];
    int E2 = in_sizes[18];
    float* out = (float*)d_out;

    cudaFuncSetAttribute(gemm_mma, cudaFuncAttributeMaxDynamicSharedMemorySize, SMEM_TOT);

    float *qbuf, *kbuf, *vbuf, *t0buf, *tmbuf, *bcbuf, *histf;
    __nv_bfloat16* wimg;
    cudaGetSymbolAddress((void**)&qbuf,  g_q);
    cudaGetSymbolAddress((void**)&kbuf,  g_k);
    cudaGetSymbolAddress((void**)&vbuf,  g_v);
    cudaGetSymbolAddress((void**)&t0buf, g_t0);
    cudaGetSymbolAddress((void**)&tmbuf, g_tm);
    cudaGetSymbolAddress((void**)&bcbuf, g_bc);
    cudaGetSymbolAddress((void**)&wimg,  g_Wimg);
    cudaGetSymbolAddress((void**)&histf, g_hist);

    float* q0 = qbuf;               float* q1 = qbuf + (size_t)NNODES * HID;
    float* k0 = kbuf;               float* k1 = kbuf + (size_t)NNODES * HID;
    float* k2 = kbuf + 2 * (size_t)NNODES * HID;
    float* v0 = vbuf;               float* v1 = vbuf + (size_t)NNODES * HID;
    float* v2 = vbuf + 2 * (size_t)NNODES * HID;
    float* tm0 = tmbuf;             float* tm1 = tmbuf + (size_t)NNODES * HID;

    #define WIMG(m, hl) (wimg + ((size_t)(m) * 2 + (hl)) * IMG_ELEMS)

    // ---- CSR build (independent of GEMMs) ----
    zero_kernel<<<(3 * NNODES / 4 + 255) / 256, 256>>>(histf, 3 * NNODES / 4);
    hist_kernel<<<(E0 + 255) / 256, 256>>>(dst0, E0, 0);
    hist_kernel<<<(E1 + 255) / 256, 256>>>(dst1, E1, 1);
    hist_kernel<<<(E2 + 255) / 256, 256>>>(dst2, E2, 2);
    scan_kernel<<<3, 1024>>>();
    scatter_kernel<<<(E0 + 255) / 256, 256>>>(src0, dst0, E0, 0);
    scatter_kernel<<<(E1 + 255) / 256, 256>>>(src1, dst1, E1, 1);
    scatter_kernel<<<(E2 + 255) / 256, 256>>>(src2, dst2, E2, 2);

    // ---- Weight prep + projection GEMMs ----
    prep_comb<<<dim3(6, 129), 128>>>(Wk, bk, Wv, bv, rel_att, rel_msg);
    convertW<<<(10 * HID * HID + 255) / 256, 256>>>(Wq, Wa);

    int gb = (M + 127) / 128;
    {
        GemmBatch b0 = {};
        b0.nsets = 3;
        b0.s[0] = { WIMG(6,0), WIMG(6,1), bq,            q0 };
        b0.s[1] = { WIMG(0,0), WIMG(0,1), bcbuf + 0*HID, k0 };
        b0.s[2] = { WIMG(1,0), WIMG(1,1), bcbuf + 1*HID, v0 };
        b0.skipv = nullptr; b0.res = nullptr;
        gemm_mma<<<gb, 256, SMEM_TOT>>>(h0, b0, M);

        GemmBatch b1 = {};
        b1.nsets = 5;
        b1.s[0] = { WIMG(7,0), WIMG(7,1), bq + HID,      q1 };
        b1.s[1] = { WIMG(2,0), WIMG(2,1), bcbuf + 2*HID, k1 };
        b1.s[2] = { WIMG(3,0), WIMG(3,1), bcbuf + 3*HID, v1 };
        b1.s[3] = { WIMG(4,0), WIMG(4,1), bcbuf + 4*HID, k2 };
        b1.s[4] = { WIMG(5,0), WIMG(5,1), bcbuf + 5*HID, v2 };
        b1.skipv = nullptr; b1.res = nullptr;
        gemm_mma<<<gb, 256, SMEM_TOT>>>(h1, b1, M);
    }

    // ---- Aggregation (warp per dst node; q from DST type: r0->q1, r1->q0, r2->q1)
    int ab = (NNODES + 7) / 8;
    // r0 (dst type 1): normalized -> tmp
    agg_kernel<<<ab, 256>>>(0, q1, k0, v0, rel_pri + 0 * NH, t0buf, nullptr, 1.f);
    // r1 (dst type 0): normalized -> tm0
    agg_kernel<<<ab, 256>>>(1, q0, k1, v1, rel_pri + 1 * NH, tm0, nullptr, 1.f);
    // r2 (dst type 1): tm1 = 0.5 * (own + r0)
    agg_kernel<<<ab, 256>>>(2, q1, k2, v2, rel_pri + 2 * NH, tm1, t0buf, 0.5f);

    // ---- Output GEMMs with skip blend ----
    {
        GemmBatch o0 = {};
        o0.nsets = 1;
        o0.s[0] = { WIMG(8,0), WIMG(8,1), ba, out };
        o0.skipv = skip + 0; o0.res = h0;
        gemm_mma<<<gb, 256, SMEM_TOT>>>(tm0, o0, M);

        GemmBatch o1 = {};
        o1.nsets = 1;
        o1.s[0] = { WIMG(9,0), WIMG(9,1), ba + HID, out + (size_t)M * HID };
        o1.skipv = skip + 1; o1.res = h1;
        gemm_mma<<<gb, 256, SMEM_TOT>>>(tm1, o1, M);
    }
}

// round 5
// speedup vs baseline: 1.5293x; 1.1168x over previous
#include <cuda_runtime.h>
#include <cuda_fp16.h>
#include <cstdint>
#include <math.h>

// Problem constants (fixed by the dataset)
#define NNODES 50000
#define HID 128
#define NH 4
#define DKH 32
#define EMAX 400000

#define AROW 136                      // padded row stride (elems) => 272B
#define IMG_ELEMS (HID * AROW)        // 17408 elems per weight image
#define IMG_BYTES (IMG_ELEMS * 2)     // 34816 B

// ---------------------------------------------------------------------------
// Scratch: __device__ globals
// ---------------------------------------------------------------------------
__device__ float g_q[2][NNODES * HID];
__device__ float g_k[3][NNODES * HID];
__device__ float g_v[3][NNODES * HID];
__device__ float g_tm[2][NNODES * HID];     // GEMM inputs for output stage
__device__ float g_Wc[6][HID * HID];
__device__ float g_bc[6][HID];
__device__ __half g_Wimg[10][IMG_ELEMS];    // single fp16 weight images
// CSR build scratch
__device__ int g_hist[3][NNODES];
__device__ int g_off[3][NNODES + 1];
__device__ int g_cur[3][NNODES];
__device__ int g_esrc[3][EMAX];

// ---------------------------------------------------------------------------
// PTX helpers: ldmatrix + mma.sync (plain sm_80+ instructions)
// ---------------------------------------------------------------------------
__device__ __forceinline__ uint32_t smem_u32(const void* p) {
    uint32_t a;
    asm("{ .reg .u64 t; cvta.to.shared.u64 t, %1; cvt.u32.u64 %0, t; }"
        : "=r"(a) : "l"(p));
    return a;
}
__device__ __forceinline__ void ldsm_x4(uint32_t* r, uint32_t addr) {
    asm volatile("ldmatrix.sync.aligned.m8n8.x4.shared.b16 {%0,%1,%2,%3}, [%4];"
                 : "=r"(r[0]), "=r"(r[1]), "=r"(r[2]), "=r"(r[3]) : "r"(addr));
}
__device__ __forceinline__ void ldsm_x2(uint32_t* r, uint32_t addr) {
    asm volatile("ldmatrix.sync.aligned.m8n8.x2.shared.b16 {%0,%1}, [%2];"
                 : "=r"(r[0]), "=r"(r[1]) : "r"(addr));
}
__device__ __forceinline__ void mma16816h(float* d, const uint32_t* a, const uint32_t* b) {
    asm volatile(
        "mma.sync.aligned.m16n8k16.row.col.f32.f16.f16.f32 "
        "{%0,%1,%2,%3}, {%4,%5,%6,%7}, {%8,%9}, {%0,%1,%2,%3};"
        : "+f"(d[0]), "+f"(d[1]), "+f"(d[2]), "+f"(d[3])
        : "r"(a[0]), "r"(a[1]), "r"(a[2]), "r"(a[3]), "r"(b[0]), "r"(b[1]));
}

// ---------------------------------------------------------------------------
// Zero a buffer
// ---------------------------------------------------------------------------
__global__ void zero_kernel(float* __restrict__ p, int n4) {
    int i = blockIdx.x * blockDim.x + threadIdx.x;
    int stride = gridDim.x * blockDim.x;
    float4 zz = make_float4(0.f, 0.f, 0.f, 0.f);
    for (; i < n4; i += stride) ((float4*)p)[i] = zz;
}

// ---------------------------------------------------------------------------
// Wc[m] = Wbase[s] @ blockdiag_h(rel[r,h]); blockIdx.y == 128 -> bias row
// ---------------------------------------------------------------------------
__global__ void prep_comb(const float* __restrict__ Wk, const float* __restrict__ bk,
                          const float* __restrict__ Wv, const float* __restrict__ bv,
                          const float* __restrict__ rel_att, const float* __restrict__ rel_msg) {
    int m = blockIdx.x;
    int r = m >> 1;
    int kind = m & 1;
    int s = (r == 0) ? 0 : 1;
    const float* Wbase = kind ? Wv : Wk;
    const float* bbase = kind ? bv : bk;
    const float* rel   = kind ? rel_msg : rel_att;

    int c = blockIdx.y;
    int j = threadIdx.x;
    int h = j >> 5;
    int jj = j & 31;
    const float* A = rel + ((size_t)r * NH + h) * DKH * DKH;

    float sum = 0.f;
    if (c < HID) {
        const float* wrow = Wbase + (size_t)s * HID * HID + (size_t)c * HID + h * DKH;
        #pragma unroll
        for (int i = 0; i < DKH; i++) sum = fmaf(wrow[i], A[i * DKH + jj], sum);
        g_Wc[m][c * HID + j] = sum;
    } else {
        const float* brow = bbase + s * HID + h * DKH;
        #pragma unroll
        for (int i = 0; i < DKH; i++) sum = fmaf(brow[i], A[i * DKH + jj], sum);
        g_bc[m][j] = sum;
    }
}

// ---------------------------------------------------------------------------
// Build transposed padded fp16 weight images: img[n*AROW + k] = W[k][n]
// ---------------------------------------------------------------------------
__global__ void convertW(const float* __restrict__ Wq, const float* __restrict__ Wa) {
    int idx = blockIdx.x * blockDim.x + threadIdx.x;
    if (idx >= 10 * HID * HID) return;
    int m = idx >> 14;
    int rem = idx & 16383;
    int n = rem >> 7;
    int k = rem & 127;

    const float* src;
    if (m < 6)       src = g_Wc[m];
    else if (m == 6) src = Wq;
    else if (m == 7) src = Wq + HID * HID;
    else if (m == 8) src = Wa;
    else             src = Wa + HID * HID;

    g_Wimg[m][n * AROW + k] = __float2half(src[k * HID + n]);
}

// ---------------------------------------------------------------------------
// CSR build: fused histogram + scan + fused scatter
// ---------------------------------------------------------------------------
__global__ void hist_all(const int* __restrict__ d0, const int* __restrict__ d1,
                         const int* __restrict__ d2, int E0, int E1, int E2) {
    int i = blockIdx.x * blockDim.x + threadIdx.x;
    int r; const int* d; int j = i;
    if (j < E0) { r = 0; d = d0; }
    else if ((j -= E0) < E1) { r = 1; d = d1; }
    else if ((j -= E1) < E2) { r = 2; d = d2; }
    else return;
    atomicAdd(&g_hist[r][d[j]], 1);
}

__global__ __launch_bounds__(1024) void scan_kernel() {
    int r = blockIdx.x;
    int t = threadIdx.x;
    __shared__ int part[1024];
    const int CH = (NNODES + 1023) / 1024;
    int beg = t * CH;
    int end = beg + CH; if (end > NNODES) end = NNODES;
    if (beg > NNODES) beg = NNODES;
    int s = 0;
    for (int i = beg; i < end; i++) s += g_hist[r][i];
    part[t] = s;
    __syncthreads();
    for (int d = 1; d < 1024; d <<= 1) {
        int v = (t >= d) ? part[t - d] : 0;
        __syncthreads();
        part[t] += v;
        __syncthreads();
    }
    int run = (t == 0) ? 0 : part[t - 1];
    for (int i = beg; i < end; i++) {
        int c = g_hist[r][i];
        g_off[r][i] = run;
        g_cur[r][i] = run;
        run += c;
    }
    if (end == NNODES) g_off[r][NNODES] = run;
}

__global__ void scatter_all(const int* __restrict__ s0, const int* __restrict__ d0,
                            const int* __restrict__ s1, const int* __restrict__ d1,
                            const int* __restrict__ s2, const int* __restrict__ d2,
                            int E0, int E1, int E2) {
    int i = blockIdx.x * blockDim.x + threadIdx.x;
    int r; const int* d; const int* s; int j = i;
    if (j < E0) { r = 0; d = d0; s = s0; }
    else if ((j -= E0) < E1) { r = 1; d = d1; s = s1; }
    else if ((j -= E1) < E2) { r = 2; d = d2; s = s2; }
    else return;
    int pos = atomicAdd(&g_cur[r][d[j]], 1);
    g_esrc[r][pos] = s[j];
}

// ---------------------------------------------------------------------------
// Batched tensor-core GEMM, fp16 x2: D = Ahi@B + Alo@B (A error-compensated).
// A split into fp16 hi/lo smem once; per set only B copied + MMAs + epilogue.
// 256 threads, 8 warps (4x2), warp tile 32x64, mma m16n8k16 f16.
// ---------------------------------------------------------------------------
struct GemmSet {
    const __half* w;
    const float* bias;
    float* C;
};
struct GemmBatch {
    GemmSet s[5];
    int nsets;
    const float* skipv;
    const float* res;
};

#define OFF_AHI 0
#define OFF_ALO IMG_BYTES
#define OFF_B   (2 * IMG_BYTES)
#define SMEM_TOT (3 * IMG_BYTES)      // 104448 B -> 2 CTAs/SM

__global__ __launch_bounds__(256) void gemm_mma(
    const float* __restrict__ A, GemmBatch batch, int M) {
    extern __shared__ char smem[];
    uint32_t sbase = smem_u32(smem);
    int tid = threadIdx.x;
    int wid = tid >> 5;
    int lane = tid & 31;
    int wr = wid >> 1;
    int wc = wid & 1;
    int row0 = blockIdx.x * 128;

    // ---- Load A tile, split into fp16 hi/lo, store padded row-major ----
    for (int i = tid; i < 128 * 64; i += 256) {
        int r = i >> 6;
        int c = (i & 63) * 2;
        int grow = row0 + r;
        float2 v = make_float2(0.f, 0.f);
        if (grow < M) v = *(const float2*)(A + (size_t)grow * HID + c);
        __half h0 = __float2half(v.x);
        __half h1 = __float2half(v.y);
        __half l0 = __float2half(v.x - __half2float(h0));
        __half l1 = __float2half(v.y - __half2float(h1));
        __half2 hp; hp.x = h0; hp.y = h1;
        __half2 lp; lp.x = l0; lp.y = l1;
        uint32_t off = (uint32_t)(r * (AROW * 2) + c * 2);
        *(__half2*)(smem + OFF_AHI + off) = hp;
        *(__half2*)(smem + OFF_ALO + off) = lp;
    }

    uint32_t a_row = (uint32_t)(wr * 32 + ((lane >> 3) & 1) * 8 + (lane & 7));
    uint32_t a_col8 = (uint32_t)((lane >> 4) * 8);
    int bl = lane & 15;
    uint32_t b_row = (uint32_t)(wc * 64 + (bl & 7));
    uint32_t b_col8 = (uint32_t)((bl >> 3) * 8);

    float alpha = 1.f, beta = 0.f;
    if (batch.skipv) {
        float sv = *batch.skipv;
        alpha = 1.f / (1.f + expf(-sv));
        beta = 1.f - alpha;
    }

    for (int s = 0; s < batch.nsets; s++) {
        __syncthreads();
        {
            const uint4* wsrc = (const uint4*)batch.s[s].w;
            uint4* wdst = (uint4*)(smem + OFF_B);
            for (int i = tid; i < IMG_BYTES / 16; i += 256) wdst[i] = wsrc[i];
        }
        __syncthreads();

        float acc[2][8][4];
        #pragma unroll
        for (int mt = 0; mt < 2; mt++)
            #pragma unroll
            for (int nt = 0; nt < 8; nt++)
                #pragma unroll
                for (int u = 0; u < 4; u++) acc[mt][nt][u] = 0.f;

        #pragma unroll
        for (int kt = 0; kt < 8; kt++) {
            uint32_t kcol = (uint32_t)(kt * 16);
            uint32_t ah[2][4], al[2][4];
            #pragma unroll
            for (int mt = 0; mt < 2; mt++) {
                uint32_t aoff = (a_row + mt * 16) * (AROW * 2) + (kcol + a_col8) * 2;
                ldsm_x4(ah[mt], sbase + OFF_AHI + aoff);
                ldsm_x4(al[mt], sbase + OFF_ALO + aoff);
            }
            #pragma unroll
            for (int nt = 0; nt < 8; nt++) {
                uint32_t boff = (b_row + nt * 8) * (AROW * 2) + (kcol + b_col8) * 2;
                uint32_t bfr[2];
                ldsm_x2(bfr, sbase + OFF_B + boff);
                #pragma unroll
                for (int mt = 0; mt < 2; mt++) {
                    mma16816h(acc[mt][nt], ah[mt], bfr);
                    mma16816h(acc[mt][nt], al[mt], bfr);
                }
            }
        }

        const float* bias = batch.s[s].bias;
        float* C = batch.s[s].C;
        const float* res = batch.res;
        #pragma unroll
        for (int mt = 0; mt < 2; mt++) {
            int row_base = row0 + wr * 32 + mt * 16 + (lane >> 2);
            #pragma unroll
            for (int half = 0; half < 2; half++) {
                int row = row_base + half * 8;
                if (row >= M) continue;
                #pragma unroll
                for (int nt = 0; nt < 8; nt++) {
                    int col = wc * 64 + nt * 8 + (lane & 3) * 2;
                    float2 o;
                    o.x = acc[mt][nt][half * 2 + 0] + bias[col];
                    o.y = acc[mt][nt][half * 2 + 1] + bias[col + 1];
                    if (res) {
                        float2 rv = *(const float2*)(res + (size_t)row * HID + col);
                        o.x = o.x * alpha + rv.x * beta;
                        o.y = o.y * alpha + rv.y * beta;
                    }
                    *(float2*)(C + (size_t)row * HID + col) = o;
                }
            }
        }
    }
}

// ---------------------------------------------------------------------------
// Aggregation: one warp per (node, type). Type-1 warps handle r0 AND r2,
// writing tm1 = 0.5*(n0 + n2) directly. Type-0 warps handle r1 -> tm0.
// ---------------------------------------------------------------------------
__device__ __forceinline__ void agg_rel(
    int rr, int node, const float* __restrict__ kb, const float* __restrict__ vb,
    float pr, int lane, float4 qv, float4& acc, float& zacc) {
    int off = g_off[rr][node];
    int deg = g_off[rr][node + 1] - off;
    const int* srcs = g_esrc[rr];

    acc = make_float4(0.f, 0.f, 0.f, 0.f);
    zacc = 0.f;

    for (int b = 0; b < deg; b += 32) {
        int cnt = deg - b; if (cnt > 32) cnt = 32;
        int myid = (lane < cnt) ? __ldg(srcs + off + b + lane) : 0;

        int s0 = __shfl_sync(0xffffffffu, myid, 0);
        float4 kv = *(const float4*)(kb + (size_t)s0 * HID + lane * 4);
        float4 vv = *(const float4*)(vb + (size_t)s0 * HID + lane * 4);

        for (int t = 0; t < cnt; t++) {
            int sn = __shfl_sync(0xffffffffu, myid, (t + 1) & 31);
            float4 kn = make_float4(0.f, 0.f, 0.f, 0.f);
            float4 vn = kn;
            if (t + 1 < cnt) {
                kn = *(const float4*)(kb + (size_t)sn * HID + lane * 4);
                vn = *(const float4*)(vb + (size_t)sn * HID + lane * 4);
            }
            float p = qv.x * kv.x + qv.y * kv.y + qv.z * kv.z + qv.w * kv.w;
            p += __shfl_xor_sync(0xffffffffu, p, 1);
            p += __shfl_xor_sync(0xffffffffu, p, 2);
            p += __shfl_xor_sync(0xffffffffu, p, 4);
            float e = __expf(p * pr);
            zacc += e;
            acc.x = fmaf(e, vv.x, acc.x);
            acc.y = fmaf(e, vv.y, acc.y);
            acc.z = fmaf(e, vv.z, acc.z);
            acc.w = fmaf(e, vv.w, acc.w);
            kv = kn; vv = vn;
        }
    }
}

__global__ __launch_bounds__(256) void agg_all(
    const float* __restrict__ q0, const float* __restrict__ q1,
    const float* __restrict__ k0, const float* __restrict__ v0,
    const float* __restrict__ k1, const float* __restrict__ v1,
    const float* __restrict__ k2, const float* __restrict__ v2,
    const float* __restrict__ rel_pri,
    float* __restrict__ tm0, float* __restrict__ tm1) {
    const int HB = NNODES / 8;    // 6250 blocks per type
    int bid = blockIdx.x;
    int wid = threadIdx.x >> 5;
    int lane = threadIdx.x & 31;
    int h = lane >> 3;
    const float RS32 = 0.17677669529663689f;   // 1/sqrt(32)

    if (bid < HB) {
        // node type 0, relation 1 (src type 1)
        int node = bid * 8 + wid;
        float4 qv = *(const float4*)(q0 + (size_t)node * HID + lane * 4);
        float pr = __ldg(rel_pri + 1 * NH + h) * RS32;
        float4 acc; float z;
        agg_rel(1, node, k1, v1, pr, lane, qv, acc, z);
        float inv = (z > 0.f) ? 1.f / z : 0.f;
        float4 o;
        o.x = acc.x * inv; o.y = acc.y * inv; o.z = acc.z * inv; o.w = acc.w * inv;
        *(float4*)(tm0 + (size_t)node * HID + lane * 4) = o;
    } else {
        // node type 1, relations 0 (src 0) and 2 (src 1)
        int node = (bid - HB) * 8 + wid;
        float4 qv = *(const float4*)(q1 + (size_t)node * HID + lane * 4);
        float pr0 = __ldg(rel_pri + 0 * NH + h) * RS32;
        float pr2 = __ldg(rel_pri + 2 * NH + h) * RS32;
        float4 a0, a2; float z0, z2;
        agg_rel(0, node, k0, v0, pr0, lane, qv, a0, z0);
        agg_rel(2, node, k2, v2, pr2, lane, qv, a2, z2);
        float i0 = (z0 > 0.f) ? 1.f / z0 : 0.f;
        float i2 = (z2 > 0.f) ? 1.f / z2 : 0.f;
        float4 o;
        o.x = 0.5f * (a0.x * i0 + a2.x * i2);
        o.y = 0.5f * (a0.y * i0 + a2.y * i2);
        o.z = 0.5f * (a0.z * i0 + a2.z * i2);
        o.w = 0.5f * (a0.w * i0 + a2.w * i2);
        *(float4*)(tm1 + (size_t)node * HID + lane * 4) = o;
    }
}

// ---------------------------------------------------------------------------
// Launch
// ---------------------------------------------------------------------------
extern "C" void kernel_launch(void* const* d_in, const int* in_sizes, int n_in,
                              void* d_out, int out_size) {
    const float* h0      = (const float*)d_in[0];
    const float* h1      = (const float*)d_in[1];
    const float* Wk      = (const float*)d_in[2];
    const float* bk      = (const float*)d_in[3];
    const float* Wq      = (const float*)d_in[4];
    const float* bq      = (const float*)d_in[5];
    const float* Wv      = (const float*)d_in[6];
    const float* bv      = (const float*)d_in[7];
    const float* Wa      = (const float*)d_in[8];
    const float* ba      = (const float*)d_in[9];
    const float* rel_att = (const float*)d_in[10];
    const float* rel_msg = (const float*)d_in[11];
    const float* rel_pri = (const float*)d_in[12];
    const float* skip    = (const float*)d_in[13];
    const int*   src0    = (const int*)d_in[14];
    const int*   dst0    = (const int*)d_in[15];
    const int*   src1    = (const int*)d_in[16];
    const int*   dst1    = (const int*)d_in[17];
    const int*   src2    = (const int*)d_in[18];
    const int*   dst2    = (const int*)d_in[19];

    int M  = in_sizes[0] / HID;
    int E0 = in_sizes[14];
    int E1 = in_sizes[16];
    int E2 = in_sizes[18];
    float* out = (float*)d_out;

    cudaFuncSetAttribute(gemm_mma, cudaFuncAttributeMaxDynamicSharedMemorySize, SMEM_TOT);

    float *qbuf, *kbuf, *vbuf, *tmbuf, *bcbuf, *histf;
    __half* wimg;
    cudaGetSymbolAddress((void**)&qbuf,  g_q);
    cudaGetSymbolAddress((void**)&kbuf,  g_k);
    cudaGetSymbolAddress((void**)&vbuf,  g_v);
    cudaGetSymbolAddress((void**)&tmbuf, g_tm);
    cudaGetSymbolAddress((void**)&bcbuf, g_bc);
    cudaGetSymbolAddress((void**)&wimg,  g_Wimg);
    cudaGetSymbolAddress((void**)&histf, g_hist);

    float* q0 = qbuf;               float* q1 = qbuf + (size_t)NNODES * HID;
    float* k0 = kbuf;               float* k1 = kbuf + (size_t)NNODES * HID;
    float* k2 = kbuf + 2 * (size_t)NNODES * HID;
    float* v0 = vbuf;               float* v1 = vbuf + (size_t)NNODES * HID;
    float* v2 = vbuf + 2 * (size_t)NNODES * HID;
    float* tm0 = tmbuf;             float* tm1 = tmbuf + (size_t)NNODES * HID;

    #define WIMG(m) (wimg + (size_t)(m) * IMG_ELEMS)

    int gb = (M + 127) / 128;
    int ET = E0 + E1 + E2;

    // 1-2: weight prep (fp32 fold, then fp16 images)
    prep_comb<<<dim3(6, 129), 128>>>(Wk, bk, Wv, bv, rel_att, rel_msg);
    convertW<<<(10 * HID * HID + 255) / 256, 256>>>(Wq, Wa);

    // 3-5: CSR histogram + scan
    zero_kernel<<<(3 * NNODES / 4 + 255) / 256, 256>>>(histf, 3 * NNODES / 4);
    hist_all<<<(ET + 255) / 256, 256>>>(dst0, dst1, dst2, E0, E1, E2);
    scan_kernel<<<3, 1024>>>();

    // 6-7: projection GEMMs (launch #6 = b0 lands in the ncu snapshot)
    {
        GemmBatch b0 = {};
        b0.nsets = 3;
        b0.s[0] = { WIMG(6), bq,            q0 };
        b0.s[1] = { WIMG(0), bcbuf + 0*HID, k0 };
        b0.s[2] = { WIMG(1), bcbuf + 1*HID, v0 };
        b0.skipv = nullptr; b0.res = nullptr;
        gemm_mma<<<gb, 256, SMEM_TOT>>>(h0, b0, M);

        GemmBatch b1 = {};
        b1.nsets = 5;
        b1.s[0] = { WIMG(7), bq + HID,      q1 };
        b1.s[1] = { WIMG(2), bcbuf + 2*HID, k1 };
        b1.s[2] = { WIMG(3), bcbuf + 3*HID, v1 };
        b1.s[3] = { WIMG(4), bcbuf + 4*HID, k2 };
        b1.s[4] = { WIMG(5), bcbuf + 5*HID, v2 };
        b1.skipv = nullptr; b1.res = nullptr;
        gemm_mma<<<gb, 256, SMEM_TOT>>>(h1, b1, M);
    }

    // 8: CSR scatter
    scatter_all<<<(ET + 255) / 256, 256>>>(src0, dst0, src1, dst1, src2, dst2,
                                           E0, E1, E2);

    // 9: fused aggregation (both node types, all 3 relations)
    agg_all<<<2 * (NNODES / 8), 256>>>(q0, q1, k0, v0, k1, v1, k2, v2,
                                       rel_pri, tm0, tm1);

    // 10-11: output GEMMs with skip blend
    {
        GemmBatch o0 = {};
        o0.nsets = 1;
        o0.s[0] = { WIMG(8), ba, out };
        o0.skipv = skip + 0; o0.res = h0;
        gemm_mma<<<gb, 256, SMEM_TOT>>>(tm0, o0, M);

        GemmBatch o1 = {};
        o1.nsets = 1;
        o1.s[0] = { WIMG(9), ba + HID, out + (size_t)M * HID };
        o1.skipv = skip + 1; o1.res = h1;
        gemm_mma<<<gb, 256, SMEM_TOT>>>(tm1, o1, M);
    }
}

// round 6
// speedup vs baseline: 1.6671x; 1.0901x over previous
#include <cuda_runtime.h>
#include <cuda_fp16.h>
#include <cstdint>
#include <math.h>

// Problem constants (fixed by the dataset)
#define NNODES 50000
#define HID 128
#define NH 4
#define DKH 32
#define EMAX 400000

#define AROW 136                      // padded row stride (elems) => 272B
#define IMG_ELEMS (HID * AROW)        // 17408 elems per weight image
#define IMG_BYTES (IMG_ELEMS * 2)     // 34816 B

// ---------------------------------------------------------------------------
// Scratch: __device__ globals
// ---------------------------------------------------------------------------
__device__ float  g_q[2][NNODES * HID];
__device__ __half g_k[3][NNODES * HID];     // fp16 folded keys
__device__ __half g_v[3][NNODES * HID];     // fp16 folded values
__device__ float  g_tm[2][NNODES * HID];
__device__ float  g_Wc[6][HID * HID];
__device__ float  g_bc[6][HID];
__device__ __half g_Wimg[10][IMG_ELEMS];
// CSR build scratch
__device__ int g_hist[3][NNODES];
__device__ int g_off[3][NNODES + 1];
__device__ int g_cur[3][NNODES];
__device__ int g_esrc[3][EMAX];

// ---------------------------------------------------------------------------
// PTX helpers: ldmatrix + mma.sync (plain sm_80+ instructions)
// ---------------------------------------------------------------------------
__device__ __forceinline__ uint32_t smem_u32(const void* p) {
    uint32_t a;
    asm("{ .reg .u64 t; cvta.to.shared.u64 t, %1; cvt.u32.u64 %0, t; }"
        : "=r"(a) : "l"(p));
    return a;
}
__device__ __forceinline__ void ldsm_x4(uint32_t* r, uint32_t addr) {
    asm volatile("ldmatrix.sync.aligned.m8n8.x4.shared.b16 {%0,%1,%2,%3}, [%4];"
                 : "=r"(r[0]), "=r"(r[1]), "=r"(r[2]), "=r"(r[3]) : "r"(addr));
}
__device__ __forceinline__ void ldsm_x2(uint32_t* r, uint32_t addr) {
    asm volatile("ldmatrix.sync.aligned.m8n8.x2.shared.b16 {%0,%1}, [%2];"
                 : "=r"(r[0]), "=r"(r[1]) : "r"(addr));
}
__device__ __forceinline__ void mma16816h(float* d, const uint32_t* a, const uint32_t* b) {
    asm volatile(
        "mma.sync.aligned.m16n8k16.row.col.f32.f16.f16.f32 "
        "{%0,%1,%2,%3}, {%4,%5,%6,%7}, {%8,%9}, {%0,%1,%2,%3};"
        : "+f"(d[0]), "+f"(d[1]), "+f"(d[2]), "+f"(d[3])
        : "r"(a[0]), "r"(a[1]), "r"(a[2]), "r"(a[3]), "r"(b[0]), "r"(b[1]));
}

// ---------------------------------------------------------------------------
// Zero a buffer
// ---------------------------------------------------------------------------
__global__ void zero_kernel(float* __restrict__ p, int n4) {
    int i = blockIdx.x * blockDim.x + threadIdx.x;
    int stride = gridDim.x * blockDim.x;
    float4 zz = make_float4(0.f, 0.f, 0.f, 0.f);
    for (; i < n4; i += stride) ((float4*)p)[i] = zz;
}

// ---------------------------------------------------------------------------
// Wc[m] = Wbase[s] @ blockdiag_h(rel[r,h]); blockIdx.y == 128 -> bias row
// ---------------------------------------------------------------------------
__global__ void prep_comb(const float* __restrict__ Wk, const float* __restrict__ bk,
                          const float* __restrict__ Wv, const float* __restrict__ bv,
                          const float* __restrict__ rel_att, const float* __restrict__ rel_msg) {
    int m = blockIdx.x;
    int r = m >> 1;
    int kind = m & 1;
    int s = (r == 0) ? 0 : 1;
    const float* Wbase = kind ? Wv : Wk;
    const float* bbase = kind ? bv : bk;
    const float* rel   = kind ? rel_msg : rel_att;

    int c = blockIdx.y;
    int j = threadIdx.x;
    int h = j >> 5;
    int jj = j & 31;
    const float* A = rel + ((size_t)r * NH + h) * DKH * DKH;

    float sum = 0.f;
    if (c < HID) {
        const float* wrow = Wbase + (size_t)s * HID * HID + (size_t)c * HID + h * DKH;
        #pragma unroll
        for (int i = 0; i < DKH; i++) sum = fmaf(wrow[i], A[i * DKH + jj], sum);
        g_Wc[m][c * HID + j] = sum;
    } else {
        const float* brow = bbase + s * HID + h * DKH;
        #pragma unroll
        for (int i = 0; i < DKH; i++) sum = fmaf(brow[i], A[i * DKH + jj], sum);
        g_bc[m][j] = sum;
    }
}

// ---------------------------------------------------------------------------
// Build transposed padded fp16 weight images: img[n*AROW + k] = W[k][n]
// ---------------------------------------------------------------------------
__global__ void convertW(const float* __restrict__ Wq, const float* __restrict__ Wa) {
    int idx = blockIdx.x * blockDim.x + threadIdx.x;
    if (idx >= 10 * HID * HID) return;
    int m = idx >> 14;
    int rem = idx & 16383;
    int n = rem >> 7;
    int k = rem & 127;

    const float* src;
    if (m < 6)       src = g_Wc[m];
    else if (m == 6) src = Wq;
    else if (m == 7) src = Wq + HID * HID;
    else if (m == 8) src = Wa;
    else             src = Wa + HID * HID;

    g_Wimg[m][n * AROW + k] = __float2half(src[k * HID + n]);
}

// ---------------------------------------------------------------------------
// CSR build: fused histogram + scan + fused scatter
// ---------------------------------------------------------------------------
__global__ void hist_all(const int* __restrict__ d0, const int* __restrict__ d1,
                         const int* __restrict__ d2, int E0, int E1, int E2) {
    int i = blockIdx.x * blockDim.x + threadIdx.x;
    int r; const int* d; int j = i;
    if (j < E0) { r = 0; d = d0; }
    else if ((j -= E0) < E1) { r = 1; d = d1; }
    else if ((j -= E1) < E2) { r = 2; d = d2; }
    else return;
    atomicAdd(&g_hist[r][d[j]], 1);
}

__global__ __launch_bounds__(1024) void scan_kernel() {
    int r = blockIdx.x;
    int t = threadIdx.x;
    __shared__ int part[1024];
    const int CH = (NNODES + 1023) / 1024;
    int beg = t * CH;
    int end = beg + CH; if (end > NNODES) end = NNODES;
    if (beg > NNODES) beg = NNODES;
    int s = 0;
    for (int i = beg; i < end; i++) s += g_hist[r][i];
    part[t] = s;
    __syncthreads();
    for (int d = 1; d < 1024; d <<= 1) {
        int v = (t >= d) ? part[t - d] : 0;
        __syncthreads();
        part[t] += v;
        __syncthreads();
    }
    int run = (t == 0) ? 0 : part[t - 1];
    for (int i = beg; i < end; i++) {
        int c = g_hist[r][i];
        g_off[r][i] = run;
        g_cur[r][i] = run;
        run += c;
    }
    if (end == NNODES) g_off[r][NNODES] = run;
}

__global__ void scatter_all(const int* __restrict__ s0, const int* __restrict__ d0,
                            const int* __restrict__ s1, const int* __restrict__ d1,
                            const int* __restrict__ s2, const int* __restrict__ d2,
                            int E0, int E1, int E2) {
    int i = blockIdx.x * blockDim.x + threadIdx.x;
    int r; const int* d; const int* s; int j = i;
    if (j < E0) { r = 0; d = d0; s = s0; }
    else if ((j -= E0) < E1) { r = 1; d = d1; s = s1; }
    else if ((j -= E1) < E2) { r = 2; d = d2; s = s2; }
    else return;
    int pos = atomicAdd(&g_cur[r][d[j]], 1);
    g_esrc[r][pos] = s[j];
}

// ---------------------------------------------------------------------------
// Batched tensor-core GEMM, fp16 x2: D = Ahi@B + Alo@B (A error-compensated).
// Per set, output goes to EITHER fp32 C or fp16 Ch.
// ---------------------------------------------------------------------------
struct GemmSet {
    const __half* w;
    const float* bias;
    float* C;        // fp32 output (nullptr if half output)
    __half* Ch;      // fp16 output (nullptr if fp32 output)
};
struct GemmBatch {
    GemmSet s[5];
    int nsets;
    const float* skipv;
    const float* res;
};

#define OFF_AHI 0
#define OFF_ALO IMG_BYTES
#define OFF_B   (2 * IMG_BYTES)
#define SMEM_TOT (3 * IMG_BYTES)      // 104448 B -> 2 CTAs/SM

__global__ __launch_bounds__(256) void gemm_mma(
    const float* __restrict__ A, GemmBatch batch, int M) {
    extern __shared__ char smem[];
    uint32_t sbase = smem_u32(smem);
    int tid = threadIdx.x;
    int wid = tid >> 5;
    int lane = tid & 31;
    int wr = wid >> 1;
    int wc = wid & 1;
    int row0 = blockIdx.x * 128;

    // ---- Load A tile, split into fp16 hi/lo, store padded row-major ----
    for (int i = tid; i < 128 * 64; i += 256) {
        int r = i >> 6;
        int c = (i & 63) * 2;
        int grow = row0 + r;
        float2 v = make_float2(0.f, 0.f);
        if (grow < M) v = *(const float2*)(A + (size_t)grow * HID + c);
        __half h0 = __float2half(v.x);
        __half h1 = __float2half(v.y);
        __half l0 = __float2half(v.x - __half2float(h0));
        __half l1 = __float2half(v.y - __half2float(h1));
        __half2 hp; hp.x = h0; hp.y = h1;
        __half2 lp; lp.x = l0; lp.y = l1;
        uint32_t off = (uint32_t)(r * (AROW * 2) + c * 2);
        *(__half2*)(smem + OFF_AHI + off) = hp;
        *(__half2*)(smem + OFF_ALO + off) = lp;
    }

    uint32_t a_row = (uint32_t)(wr * 32 + ((lane >> 3) & 1) * 8 + (lane & 7));
    uint32_t a_col8 = (uint32_t)((lane >> 4) * 8);
    int bl = lane & 15;
    uint32_t b_row = (uint32_t)(wc * 64 + (bl & 7));
    uint32_t b_col8 = (uint32_t)((bl >> 3) * 8);

    float alpha = 1.f, beta = 0.f;
    if (batch.skipv) {
        float sv = *batch.skipv;
        alpha = 1.f / (1.f + expf(-sv));
        beta = 1.f - alpha;
    }

    for (int s = 0; s < batch.nsets; s++) {
        __syncthreads();
        {
            const uint4* wsrc = (const uint4*)batch.s[s].w;
            uint4* wdst = (uint4*)(smem + OFF_B);
            for (int i = tid; i < IMG_BYTES / 16; i += 256) wdst[i] = wsrc[i];
        }
        __syncthreads();

        float acc[2][8][4];
        #pragma unroll
        for (int mt = 0; mt < 2; mt++)
            #pragma unroll
            for (int nt = 0; nt < 8; nt++)
                #pragma unroll
                for (int u = 0; u < 4; u++) acc[mt][nt][u] = 0.f;

        #pragma unroll
        for (int kt = 0; kt < 8; kt++) {
            uint32_t kcol = (uint32_t)(kt * 16);
            uint32_t ah[2][4], al[2][4];
            #pragma unroll
            for (int mt = 0; mt < 2; mt++) {
                uint32_t aoff = (a_row + mt * 16) * (AROW * 2) + (kcol + a_col8) * 2;
                ldsm_x4(ah[mt], sbase + OFF_AHI + aoff);
                ldsm_x4(al[mt], sbase + OFF_ALO + aoff);
            }
            #pragma unroll
            for (int nt = 0; nt < 8; nt++) {
                uint32_t boff = (b_row + nt * 8) * (AROW * 2) + (kcol + b_col8) * 2;
                uint32_t bfr[2];
                ldsm_x2(bfr, sbase + OFF_B + boff);
                #pragma unroll
                for (int mt = 0; mt < 2; mt++) {
                    mma16816h(acc[mt][nt], ah[mt], bfr);
                    mma16816h(acc[mt][nt], al[mt], bfr);
                }
            }
        }

        const float* bias = batch.s[s].bias;
        float* C = batch.s[s].C;
        __half* Ch = batch.s[s].Ch;
        const float* res = batch.res;
        #pragma unroll
        for (int mt = 0; mt < 2; mt++) {
            int row_base = row0 + wr * 32 + mt * 16 + (lane >> 2);
            #pragma unroll
            for (int half = 0; half < 2; half++) {
                int row = row_base + half * 8;
                if (row >= M) continue;
                #pragma unroll
                for (int nt = 0; nt < 8; nt++) {
                    int col = wc * 64 + nt * 8 + (lane & 3) * 2;
                    float2 o;
                    o.x = acc[mt][nt][half * 2 + 0] + bias[col];
                    o.y = acc[mt][nt][half * 2 + 1] + bias[col + 1];
                    if (res) {
                        float2 rv = *(const float2*)(res + (size_t)row * HID + col);
                        o.x = o.x * alpha + rv.x * beta;
                        o.y = o.y * alpha + rv.y * beta;
                    }
                    if (Ch) {
                        *(__half2*)(Ch + (size_t)row * HID + col) =
                            __floats2half2_rn(o.x, o.y);
                    } else {
                        *(float2*)(C + (size_t)row * HID + col) = o;
                    }
                }
            }
        }
    }
}

// ---------------------------------------------------------------------------
// Aggregation: one warp per (node, type); k/v gathered as fp16 (half traffic).
// ---------------------------------------------------------------------------
__device__ __forceinline__ float4 ld_half8_as_f4(const __half* base, int lane) {
    uint2 raw = *((const uint2*)base + lane);
    __half2 p0 = *(__half2*)&raw.x;
    __half2 p1 = *(__half2*)&raw.y;
    float2 f0 = __half22float2(p0);
    float2 f1 = __half22float2(p1);
    return make_float4(f0.x, f0.y, f1.x, f1.y);
}

__device__ __forceinline__ void agg_rel(
    int rr, int node, const __half* __restrict__ kb, const __half* __restrict__ vb,
    float pr, int lane, float4 qv, float4& acc, float& zacc) {
    int off = g_off[rr][node];
    int deg = g_off[rr][node + 1] - off;
    const int* srcs = g_esrc[rr];

    acc = make_float4(0.f, 0.f, 0.f, 0.f);
    zacc = 0.f;

    for (int b = 0; b < deg; b += 32) {
        int cnt = deg - b; if (cnt > 32) cnt = 32;
        int myid = (lane < cnt) ? __ldg(srcs + off + b + lane) : 0;

        int s0 = __shfl_sync(0xffffffffu, myid, 0);
        float4 kv = ld_half8_as_f4(kb + (size_t)s0 * HID, lane);
        float4 vv = ld_half8_as_f4(vb + (size_t)s0 * HID, lane);

        for (int t = 0; t < cnt; t++) {
            int sn = __shfl_sync(0xffffffffu, myid, (t + 1) & 31);
            float4 kn = make_float4(0.f, 0.f, 0.f, 0.f);
            float4 vn = kn;
            if (t + 1 < cnt) {
                kn = ld_half8_as_f4(kb + (size_t)sn * HID, lane);
                vn = ld_half8_as_f4(vb + (size_t)sn * HID, lane);
            }
            float p = qv.x * kv.x + qv.y * kv.y + qv.z * kv.z + qv.w * kv.w;
            p += __shfl_xor_sync(0xffffffffu, p, 1);
            p += __shfl_xor_sync(0xffffffffu, p, 2);
            p += __shfl_xor_sync(0xffffffffu, p, 4);
            float e = __expf(p * pr);
            zacc += e;
            acc.x = fmaf(e, vv.x, acc.x);
            acc.y = fmaf(e, vv.y, acc.y);
            acc.z = fmaf(e, vv.z, acc.z);
            acc.w = fmaf(e, vv.w, acc.w);
            kv = kn; vv = vn;
        }
    }
}

__global__ __launch_bounds__(256) void agg_all(
    const float* __restrict__ q0, const float* __restrict__ q1,
    const __half* __restrict__ k0, const __half* __restrict__ v0,
    const __half* __restrict__ k1, const __half* __restrict__ v1,
    const __half* __restrict__ k2, const __half* __restrict__ v2,
    const float* __restrict__ rel_pri,
    float* __restrict__ tm0, float* __restrict__ tm1) {
    const int HB = NNODES / 8;
    int bid = blockIdx.x;
    int wid = threadIdx.x >> 5;
    int lane = threadIdx.x & 31;
    int h = lane >> 3;
    const float RS32 = 0.17677669529663689f;

    if (bid < HB) {
        int node = bid * 8 + wid;
        float4 qv = *(const float4*)(q0 + (size_t)node * HID + lane * 4);
        float pr = __ldg(rel_pri + 1 * NH + h) * RS32;
        float4 acc; float z;
        agg_rel(1, node, k1, v1, pr, lane, qv, acc, z);
        float inv = (z > 0.f) ? 1.f / z : 0.f;
        float4 o;
        o.x = acc.x * inv; o.y = acc.y * inv; o.z = acc.z * inv; o.w = acc.w * inv;
        *(float4*)(tm0 + (size_t)node * HID + lane * 4) = o;
    } else {
        int node = (bid - HB) * 8 + wid;
        float4 qv = *(const float4*)(q1 + (size_t)node * HID + lane * 4);
        float pr0 = __ldg(rel_pri + 0 * NH + h) * RS32;
        float pr2 = __ldg(rel_pri + 2 * NH + h) * RS32;
        float4 a0, a2; float z0, z2;
        agg_rel(0, node, k0, v0, pr0, lane, qv, a0, z0);
        agg_rel(2, node, k2, v2, pr2, lane, qv, a2, z2);
        float i0 = (z0 > 0.f) ? 1.f / z0 : 0.f;
        float i2 = (z2 > 0.f) ? 1.f / z2 : 0.f;
        float4 o;
        o.x = 0.5f * (a0.x * i0 + a2.x * i2);
        o.y = 0.5f * (a0.y * i0 + a2.y * i2);
        o.z = 0.5f * (a0.z * i0 + a2.z * i2);
        o.w = 0.5f * (a0.w * i0 + a2.w * i2);
        *(float4*)(tm1 + (size_t)node * HID + lane * 4) = o;
    }
}

// ---------------------------------------------------------------------------
// Launch
// ---------------------------------------------------------------------------
extern "C" void kernel_launch(void* const* d_in, const int* in_sizes, int n_in,
                              void* d_out, int out_size) {
    const float* h0      = (const float*)d_in[0];
    const float* h1      = (const float*)d_in[1];
    const float* Wk      = (const float*)d_in[2];
    const float* bk      = (const float*)d_in[3];
    const float* Wq      = (const float*)d_in[4];
    const float* bq      = (const float*)d_in[5];
    const float* Wv      = (const float*)d_in[6];
    const float* bv      = (const float*)d_in[7];
    const float* Wa      = (const float*)d_in[8];
    const float* ba      = (const float*)d_in[9];
    const float* rel_att = (const float*)d_in[10];
    const float* rel_msg = (const float*)d_in[11];
    const float* rel_pri = (const float*)d_in[12];
    const float* skip    = (const float*)d_in[13];
    const int*   src0    = (const int*)d_in[14];
    const int*   dst0    = (const int*)d_in[15];
    const int*   src1    = (const int*)d_in[16];
    const int*   dst1    = (const int*)d_in[17];
    const int*   src2    = (const int*)d_in[18];
    const int*   dst2    = (const int*)d_in[19];

    int M  = in_sizes[0] / HID;
    int E0 = in_sizes[14];
    int E1 = in_sizes[16];
    int E2 = in_sizes[18];
    float* out = (float*)d_out;

    cudaFuncSetAttribute(gemm_mma, cudaFuncAttributeMaxDynamicSharedMemorySize, SMEM_TOT);

    float *qbuf, *tmbuf, *bcbuf, *histf;
    __half *kbuf, *vbuf, *wimg;
    cudaGetSymbolAddress((void**)&qbuf,  g_q);
    cudaGetSymbolAddress((void**)&kbuf,  g_k);
    cudaGetSymbolAddress((void**)&vbuf,  g_v);
    cudaGetSymbolAddress((void**)&tmbuf, g_tm);
    cudaGetSymbolAddress((void**)&bcbuf, g_bc);
    cudaGetSymbolAddress((void**)&wimg,  g_Wimg);
    cudaGetSymbolAddress((void**)&histf, g_hist);

    float* q0 = qbuf;                float* q1 = qbuf + (size_t)NNODES * HID;
    __half* k0 = kbuf;               __half* k1 = kbuf + (size_t)NNODES * HID;
    __half* k2 = kbuf + 2 * (size_t)NNODES * HID;
    __half* v0 = vbuf;               __half* v1 = vbuf + (size_t)NNODES * HID;
    __half* v2 = vbuf + 2 * (size_t)NNODES * HID;
    float* tm0 = tmbuf;              float* tm1 = tmbuf + (size_t)NNODES * HID;

    #define WIMG(m) (wimg + (size_t)(m) * IMG_ELEMS)

    int gb = (M + 127) / 128;
    int ET = E0 + E1 + E2;

    // 1-3: weight prep + hist zero
    prep_comb<<<dim3(6, 129), 128>>>(Wk, bk, Wv, bv, rel_att, rel_msg);
    convertW<<<(10 * HID * HID + 255) / 256, 256>>>(Wq, Wa);
    zero_kernel<<<(3 * NNODES / 4 + 255) / 256, 256>>>(histf, 3 * NNODES / 4);

    // 4-5: projection GEMMs (position 4 => gemm b0 is the ncu-profiled launch)
    {
        GemmBatch b0 = {};
        b0.nsets = 3;
        b0.s[0] = { WIMG(6), bq,            q0,      nullptr };
        b0.s[1] = { WIMG(0), bcbuf + 0*HID, nullptr, k0 };
        b0.s[2] = { WIMG(1), bcbuf + 1*HID, nullptr, v0 };
        b0.skipv = nullptr; b0.res = nullptr;
        gemm_mma<<<gb, 256, SMEM_TOT>>>(h0, b0, M);

        GemmBatch b1 = {};
        b1.nsets = 5;
        b1.s[0] = { WIMG(7), bq + HID,      q1,      nullptr };
        b1.s[1] = { WIMG(2), bcbuf + 2*HID, nullptr, k1 };
        b1.s[2] = { WIMG(3), bcbuf + 3*HID, nullptr, v1 };
        b1.s[3] = { WIMG(4), bcbuf + 4*HID, nullptr, k2 };
        b1.s[4] = { WIMG(5), bcbuf + 5*HID, nullptr, v2 };
        b1.skipv = nullptr; b1.res = nullptr;
        gemm_mma<<<gb, 256, SMEM_TOT>>>(h1, b1, M);
    }

    // 6-8: CSR build
    hist_all<<<(ET + 255) / 256, 256>>>(dst0, dst1, dst2, E0, E1, E2);
    scan_kernel<<<3, 1024>>>();
    scatter_all<<<(ET + 255) / 256, 256>>>(src0, dst0, src1, dst1, src2, dst2,
                                           E0, E1, E2);

    // 9: fused aggregation
    agg_all<<<2 * (NNODES / 8), 256>>>(q0, q1, k0, v0, k1, v1, k2, v2,
                                       rel_pri, tm0, tm1);

    // 10-11: output GEMMs with skip blend
    {
        GemmBatch o0 = {};
        o0.nsets = 1;
        o0.s[0] = { WIMG(8), ba, out, nullptr };
        o0.skipv = skip + 0; o0.res = h0;
        gemm_mma<<<gb, 256, SMEM_TOT>>>(tm0, o0, M);

        GemmBatch o1 = {};
        o1.nsets = 1;
        o1.s[0] = { WIMG(9), ba + HID, out + (size_t)M * HID, nullptr };
        o1.skipv = skip + 1; o1.res = h1;
        gemm_mma<<<gb, 256, SMEM_TOT>>>(tm1, o1, M);
    }
}

// round 7
// speedup vs baseline: 1.7026x; 1.0213x over previous
#include <cuda_runtime.h>
#include <cuda_fp16.h>
#include <cstdint>
#include <math.h>

// Problem constants (fixed by the dataset)
#define NNODES 50000
#define HID 128
#define NH 4
#define DKH 32
#define EMAX 400000

#define IMG_ELEMS (HID * HID)         // dense swizzled image: 16384 halves
#define IMG_BYTES (IMG_ELEMS * 2)     // 32768 B

// ---------------------------------------------------------------------------
// Scratch: __device__ globals
// ---------------------------------------------------------------------------
__device__ float  g_q[2][NNODES * HID];
__device__ __half g_k[3][NNODES * HID];     // fp16 folded keys
__device__ __half g_v[3][NNODES * HID];     // fp16 folded values
__device__ float  g_tm[2][NNODES * HID];
__device__ float  g_Wc[6][HID * HID];
__device__ float  g_bc[6][HID];
__device__ __half g_Wimg[10][IMG_ELEMS];    // swizzled fp16 weight images
// CSR build scratch
__device__ int g_hist[3][NNODES];
__device__ int g_off[3][NNODES + 1];
__device__ int g_cur[3][NNODES];
__device__ int g_esrc[3][EMAX];

// Swizzled half-index within a 128x128 image: row-major 256B rows,
// 16B chunks XOR-swizzled by row&7 (conflict-free for ldmatrix).
__device__ __host__ __forceinline__ int swz_idx(int row, int k) {
    return row * 128 + ((((k >> 3) ^ (row & 7)) << 3) | (k & 7));
}

// ---------------------------------------------------------------------------
// PTX helpers: ldmatrix + mma.sync + cp.async (plain sm_80+ instructions)
// ---------------------------------------------------------------------------
__device__ __forceinline__ uint32_t smem_u32(const void* p) {
    uint32_t a;
    asm("{ .reg .u64 t; cvta.to.shared.u64 t, %1; cvt.u32.u64 %0, t; }"
        : "=r"(a) : "l"(p));
    return a;
}
__device__ __forceinline__ void ldsm_x4(uint32_t* r, uint32_t addr) {
    asm volatile("ldmatrix.sync.aligned.m8n8.x4.shared.b16 {%0,%1,%2,%3}, [%4];"
                 : "=r"(r[0]), "=r"(r[1]), "=r"(r[2]), "=r"(r[3]) : "r"(addr));
}
__device__ __forceinline__ void ldsm_x2(uint32_t* r, uint32_t addr) {
    asm volatile("ldmatrix.sync.aligned.m8n8.x2.shared.b16 {%0,%1}, [%2];"
                 : "=r"(r[0]), "=r"(r[1]) : "r"(addr));
}
__device__ __forceinline__ void mma16816h(float* d, const uint32_t* a, const uint32_t* b) {
    asm volatile(
        "mma.sync.aligned.m16n8k16.row.col.f32.f16.f16.f32 "
        "{%0,%1,%2,%3}, {%4,%5,%6,%7}, {%8,%9}, {%0,%1,%2,%3};"
        : "+f"(d[0]), "+f"(d[1]), "+f"(d[2]), "+f"(d[3])
        : "r"(a[0]), "r"(a[1]), "r"(a[2]), "r"(a[3]), "r"(b[0]), "r"(b[1]));
}
#define CP_ASYNC16(dst, src) \
    asm volatile("cp.async.cg.shared.global [%0], [%1], 16;" :: "r"(dst), "l"(src))
#define CP_COMMIT() asm volatile("cp.async.commit_group;" ::: "memory")
#define CP_WAIT0()  asm volatile("cp.async.wait_group 0;" ::: "memory")

// ---------------------------------------------------------------------------
// Zero a buffer
// ---------------------------------------------------------------------------
__global__ void zero_kernel(float* __restrict__ p, int n4) {
    int i = blockIdx.x * blockDim.x + threadIdx.x;
    int stride = gridDim.x * blockDim.x;
    float4 zz = make_float4(0.f, 0.f, 0.f, 0.f);
    for (; i < n4; i += stride) ((float4*)p)[i] = zz;
}

// ---------------------------------------------------------------------------
// Wc[m] = Wbase[s] @ blockdiag_h(rel[r,h]); blockIdx.y == 128 -> bias row
// ---------------------------------------------------------------------------
__global__ void prep_comb(const float* __restrict__ Wk, const float* __restrict__ bk,
                          const float* __restrict__ Wv, const float* __restrict__ bv,
                          const float* __restrict__ rel_att, const float* __restrict__ rel_msg) {
    int m = blockIdx.x;
    int r = m >> 1;
    int kind = m & 1;
    int s = (r == 0) ? 0 : 1;
    const float* Wbase = kind ? Wv : Wk;
    const float* bbase = kind ? bv : bk;
    const float* rel   = kind ? rel_msg : rel_att;

    int c = blockIdx.y;
    int j = threadIdx.x;
    int h = j >> 5;
    int jj = j & 31;
    const float* A = rel + ((size_t)r * NH + h) * DKH * DKH;

    float sum = 0.f;
    if (c < HID) {
        const float* wrow = Wbase + (size_t)s * HID * HID + (size_t)c * HID + h * DKH;
        #pragma unroll
        for (int i = 0; i < DKH; i++) sum = fmaf(wrow[i], A[i * DKH + jj], sum);
        g_Wc[m][c * HID + j] = sum;
    } else {
        const float* brow = bbase + s * HID + h * DKH;
        #pragma unroll
        for (int i = 0; i < DKH; i++) sum = fmaf(brow[i], A[i * DKH + jj], sum);
        g_bc[m][j] = sum;
    }
}

// ---------------------------------------------------------------------------
// Build transposed SWIZZLED fp16 weight images: img[swz(n,k)] = W[k][n]
// ---------------------------------------------------------------------------
__global__ void convertW(const float* __restrict__ Wq, const float* __restrict__ Wa) {
    int idx = blockIdx.x * blockDim.x + threadIdx.x;
    if (idx >= 10 * HID * HID) return;
    int m = idx >> 14;
    int rem = idx & 16383;
    int n = rem >> 7;
    int k = rem & 127;

    const float* src;
    if (m < 6)       src = g_Wc[m];
    else if (m == 6) src = Wq;
    else if (m == 7) src = Wq + HID * HID;
    else if (m == 8) src = Wa;
    else             src = Wa + HID * HID;

    g_Wimg[m][swz_idx(n, k)] = __float2half(src[k * HID + n]);
}

// ---------------------------------------------------------------------------
// CSR build: fused histogram + scan + fused scatter
// ---------------------------------------------------------------------------
__global__ void hist_all(const int* __restrict__ d0, const int* __restrict__ d1,
                         const int* __restrict__ d2, int E0, int E1, int E2) {
    int i = blockIdx.x * blockDim.x + threadIdx.x;
    int r; const int* d; int j = i;
    if (j < E0) { r = 0; d = d0; }
    else if ((j -= E0) < E1) { r = 1; d = d1; }
    else if ((j -= E1) < E2) { r = 2; d = d2; }
    else return;
    atomicAdd(&g_hist[r][d[j]], 1);
}

__global__ __launch_bounds__(1024) void scan_kernel() {
    int r = blockIdx.x;
    int t = threadIdx.x;
    __shared__ int part[1024];
    const int CH = (NNODES + 1023) / 1024;
    int beg = t * CH;
    int end = beg + CH; if (end > NNODES) end = NNODES;
    if (beg > NNODES) beg = NNODES;
    int s = 0;
    for (int i = beg; i < end; i++) s += g_hist[r][i];
    part[t] = s;
    __syncthreads();
    for (int d = 1; d < 1024; d <<= 1) {
        int v = (t >= d) ? part[t - d] : 0;
        __syncthreads();
        part[t] += v;
        __syncthreads();
    }
    int run = (t == 0) ? 0 : part[t - 1];
    for (int i = beg; i < end; i++) {
        int c = g_hist[r][i];
        g_off[r][i] = run;
        g_cur[r][i] = run;
        run += c;
    }
    if (end == NNODES) g_off[r][NNODES] = run;
}

__global__ void scatter_all(const int* __restrict__ s0, const int* __restrict__ d0,
                            const int* __restrict__ s1, const int* __restrict__ d1,
                            const int* __restrict__ s2, const int* __restrict__ d2,
                            int E0, int E1, int E2) {
    int i = blockIdx.x * blockDim.x + threadIdx.x;
    int r; const int* d; const int* s; int j = i;
    if (j < E0) { r = 0; d = d0; s = s0; }
    else if ((j -= E0) < E1) { r = 1; d = d1; s = s1; }
    else if ((j -= E1) < E2) { r = 2; d = d2; s = s2; }
    else return;
    int pos = atomicAdd(&g_cur[r][d[j]], 1);
    g_esrc[r][pos] = s[j];
}

// ---------------------------------------------------------------------------
// Batched tensor-core GEMM, fp16 x2: D = Ahi@B + Alo@B. Swizzled smem images
// (32KB each: Ahi, Alo, B) -> 96KB total -> 2 CTAs/SM. cp.async B copies.
// ---------------------------------------------------------------------------
struct GemmSet {
    const __half* w;
    const float* bias;
    float* C;        // fp32 output (nullptr if half output)
    __half* Ch;      // fp16 output (nullptr if fp32 output)
};
struct GemmBatch {
    GemmSet s[5];
    int nsets;
    const float* skipv;
    const float* res;
};

#define OFF_AHI 0
#define OFF_ALO IMG_BYTES
#define OFF_B   (2 * IMG_BYTES)
#define SMEM_TOT (3 * IMG_BYTES)      // 98304 B -> 2 CTAs/SM

__global__ __launch_bounds__(256, 2) void gemm_mma(
    const float* __restrict__ A, GemmBatch batch, int M) {
    extern __shared__ char smem[];
    uint32_t sbase = smem_u32(smem);
    int tid = threadIdx.x;
    int wid = tid >> 5;
    int lane = tid & 31;
    int wr = wid >> 1;
    int wc = wid & 1;
    int row0 = blockIdx.x * 128;

    // Kick off B[0] copy first (cp.async, overlaps with A conversion)
    {
        const char* wsrc = (const char*)batch.s[0].w;
        for (int i = tid; i < IMG_BYTES / 16; i += 256)
            CP_ASYNC16(sbase + OFF_B + i * 16, wsrc + i * 16);
        CP_COMMIT();
    }

    // ---- Load A tile, split into fp16 hi/lo, store swizzled ----
    for (int i = tid; i < 128 * 64; i += 256) {
        int r = i >> 6;
        int c = (i & 63) * 2;
        int grow = row0 + r;
        float2 v = make_float2(0.f, 0.f);
        if (grow < M) v = *(const float2*)(A + (size_t)grow * HID + c);
        __half h0 = __float2half(v.x);
        __half h1 = __float2half(v.y);
        __half l0 = __float2half(v.x - __half2float(h0));
        __half l1 = __float2half(v.y - __half2float(h1));
        __half2 hp; hp.x = h0; hp.y = h1;
        __half2 lp; lp.x = l0; lp.y = l1;
        uint32_t off = (uint32_t)(swz_idx(r, c) * 2);
        *(__half2*)(smem + OFF_AHI + off) = hp;
        *(__half2*)(smem + OFF_ALO + off) = lp;
    }

    // ldmatrix addressing (swizzled):
    // A x4: rows a_rowbase + mt*16 (+8 per lane>>3 bit), chunk kt*2 + (lane>>4)
    uint32_t a_rowbase = (uint32_t)(wr * 32 + ((lane >> 3) & 1) * 8 + (lane & 7));
    uint32_t a_chunkoff = (uint32_t)(lane >> 4);
    uint32_t a_phase = a_rowbase & 7;
    // B x2: rows b_rowbase + nt*8, chunk kt*2 + (bl>>3)
    int bl = lane & 15;
    uint32_t b_rowbase = (uint32_t)(wc * 64 + (bl & 7));
    uint32_t b_chunkoff = (uint32_t)(bl >> 3);
    uint32_t b_phase = b_rowbase & 7;

    float alpha = 1.f, beta = 0.f;
    if (batch.skipv) {
        float sv = *batch.skipv;
        alpha = 1.f / (1.f + expf(-sv));
        beta = 1.f - alpha;
    }

    for (int s = 0; s < batch.nsets; s++) {
        CP_WAIT0();
        __syncthreads();

        float acc[2][8][4];
        #pragma unroll
        for (int mt = 0; mt < 2; mt++)
            #pragma unroll
            for (int nt = 0; nt < 8; nt++)
                #pragma unroll
                for (int u = 0; u < 4; u++) acc[mt][nt][u] = 0.f;

        #pragma unroll
        for (int kt = 0; kt < 8; kt++) {
            uint32_t ac = (uint32_t)(kt * 2) + a_chunkoff;
            uint32_t bc = (uint32_t)(kt * 2) + b_chunkoff;
            uint32_t ah[2][4], al[2][4];
            #pragma unroll
            for (int mt = 0; mt < 2; mt++) {
                uint32_t aoff = (a_rowbase + mt * 16) * 256 + ((ac ^ a_phase) << 4);
                ldsm_x4(ah[mt], sbase + OFF_AHI + aoff);
                ldsm_x4(al[mt], sbase + OFF_ALO + aoff);
            }
            #pragma unroll
            for (int nt = 0; nt < 8; nt++) {
                uint32_t boff = (b_rowbase + nt * 8) * 256 + ((bc ^ b_phase) << 4);
                uint32_t bfr[2];
                ldsm_x2(bfr, sbase + OFF_B + boff);
                #pragma unroll
                for (int mt = 0; mt < 2; mt++) {
                    mma16816h(acc[mt][nt], ah[mt], bfr);
                    mma16816h(acc[mt][nt], al[mt], bfr);
                }
            }
        }

        // Prefetch next set's B while doing the epilogue
        __syncthreads();
        if (s + 1 < batch.nsets) {
            const char* wsrc = (const char*)batch.s[s + 1].w;
            for (int i = tid; i < IMG_BYTES / 16; i += 256)
                CP_ASYNC16(sbase + OFF_B + i * 16, wsrc + i * 16);
            CP_COMMIT();
        }

        const float* bias = batch.s[s].bias;
        float* C = batch.s[s].C;
        __half* Ch = batch.s[s].Ch;
        const float* res = batch.res;
        #pragma unroll
        for (int mt = 0; mt < 2; mt++) {
            int row_base = row0 + wr * 32 + mt * 16 + (lane >> 2);
            #pragma unroll
            for (int half = 0; half < 2; half++) {
                int row = row_base + half * 8;
                if (row >= M) continue;
                #pragma unroll
                for (int nt = 0; nt < 8; nt++) {
                    int col = wc * 64 + nt * 8 + (lane & 3) * 2;
                    float2 o;
                    o.x = acc[mt][nt][half * 2 + 0] + bias[col];
                    o.y = acc[mt][nt][half * 2 + 1] + bias[col + 1];
                    if (res) {
                        float2 rv = *(const float2*)(res + (size_t)row * HID + col);
                        o.x = o.x * alpha + rv.x * beta;
                        o.y = o.y * alpha + rv.y * beta;
                    }
                    if (Ch) {
                        *(__half2*)(Ch + (size_t)row * HID + col) =
                            __floats2half2_rn(o.x, o.y);
                    } else {
                        *(float2*)(C + (size_t)row * HID + col) = o;
                    }
                }
            }
        }
    }
}

// ---------------------------------------------------------------------------
// Aggregation: one warp per (node, type); k/v gathered as fp16.
// ---------------------------------------------------------------------------
__device__ __forceinline__ float4 ld_half8_as_f4(const __half* base, int lane) {
    uint2 raw = *((const uint2*)base + lane);
    __half2 p0 = *(__half2*)&raw.x;
    __half2 p1 = *(__half2*)&raw.y;
    float2 f0 = __half22float2(p0);
    float2 f1 = __half22float2(p1);
    return make_float4(f0.x, f0.y, f1.x, f1.y);
}

__device__ __forceinline__ void agg_rel(
    int rr, int node, const __half* __restrict__ kb, const __half* __restrict__ vb,
    float pr, int lane, float4 qv, float4& acc, float& zacc) {
    int off = g_off[rr][node];
    int deg = g_off[rr][node + 1] - off;
    const int* srcs = g_esrc[rr];

    acc = make_float4(0.f, 0.f, 0.f, 0.f);
    zacc = 0.f;

    for (int b = 0; b < deg; b += 32) {
        int cnt = deg - b; if (cnt > 32) cnt = 32;
        int myid = (lane < cnt) ? __ldg(srcs + off + b + lane) : 0;

        int s0 = __shfl_sync(0xffffffffu, myid, 0);
        float4 kv = ld_half8_as_f4(kb + (size_t)s0 * HID, lane);
        float4 vv = ld_half8_as_f4(vb + (size_t)s0 * HID, lane);

        for (int t = 0; t < cnt; t++) {
            int sn = __shfl_sync(0xffffffffu, myid, (t + 1) & 31);
            float4 kn = make_float4(0.f, 0.f, 0.f, 0.f);
            float4 vn = kn;
            if (t + 1 < cnt) {
                kn = ld_half8_as_f4(kb + (size_t)sn * HID, lane);
                vn = ld_half8_as_f4(vb + (size_t)sn * HID, lane);
            }
            float p = qv.x * kv.x + qv.y * kv.y + qv.z * kv.z + qv.w * kv.w;
            p += __shfl_xor_sync(0xffffffffu, p, 1);
            p += __shfl_xor_sync(0xffffffffu, p, 2);
            p += __shfl_xor_sync(0xffffffffu, p, 4);
            float e = __expf(p * pr);
            zacc += e;
            acc.x = fmaf(e, vv.x, acc.x);
            acc.y = fmaf(e, vv.y, acc.y);
            acc.z = fmaf(e, vv.z, acc.z);
            acc.w = fmaf(e, vv.w, acc.w);
            kv = kn; vv = vn;
        }
    }
}

__global__ __launch_bounds__(256) void agg_all(
    const float* __restrict__ q0, const float* __restrict__ q1,
    const __half* __restrict__ k0, const __half* __restrict__ v0,
    const __half* __restrict__ k1, const __half* __restrict__ v1,
    const __half* __restrict__ k2, const __half* __restrict__ v2,
    const float* __restrict__ rel_pri,
    float* __restrict__ tm0, float* __restrict__ tm1) {
    const int HB = NNODES / 8;
    int bid = blockIdx.x;
    int wid = threadIdx.x >> 5;
    int lane = threadIdx.x & 31;
    int h = lane >> 3;
    const float RS32 = 0.17677669529663689f;

    if (bid < HB) {
        int node = bid * 8 + wid;
        float4 qv = *(const float4*)(q0 + (size_t)node * HID + lane * 4);
        float pr = __ldg(rel_pri + 1 * NH + h) * RS32;
        float4 acc; float z;
        agg_rel(1, node, k1, v1, pr, lane, qv, acc, z);
        float inv = (z > 0.f) ? 1.f / z : 0.f;
        float4 o;
        o.x = acc.x * inv; o.y = acc.y * inv; o.z = acc.z * inv; o.w = acc.w * inv;
        *(float4*)(tm0 + (size_t)node * HID + lane * 4) = o;
    } else {
        int node = (bid - HB) * 8 + wid;
        float4 qv = *(const float4*)(q1 + (size_t)node * HID + lane * 4);
        float pr0 = __ldg(rel_pri + 0 * NH + h) * RS32;
        float pr2 = __ldg(rel_pri + 2 * NH + h) * RS32;
        float4 a0, a2; float z0, z2;
        agg_rel(0, node, k0, v0, pr0, lane, qv, a0, z0);
        agg_rel(2, node, k2, v2, pr2, lane, qv, a2, z2);
        float i0 = (z0 > 0.f) ? 1.f / z0 : 0.f;
        float i2 = (z2 > 0.f) ? 1.f / z2 : 0.f;
        float4 o;
        o.x = 0.5f * (a0.x * i0 + a2.x * i2);
        o.y = 0.5f * (a0.y * i0 + a2.y * i2);
        o.z = 0.5f * (a0.z * i0 + a2.z * i2);
        o.w = 0.5f * (a0.w * i0 + a2.w * i2);
        *(float4*)(tm1 + (size_t)node * HID + lane * 4) = o;
    }
}

// ---------------------------------------------------------------------------
// Launch
// ---------------------------------------------------------------------------
extern "C" void kernel_launch(void* const* d_in, const int* in_sizes, int n_in,
                              void* d_out, int out_size) {
    const float* h0      = (const float*)d_in[0];
    const float* h1      = (const float*)d_in[1];
    const float* Wk      = (const float*)d_in[2];
    const float* bk      = (const float*)d_in[3];
    const float* Wq      = (const float*)d_in[4];
    const float* bq      = (const float*)d_in[5];
    const float* Wv      = (const float*)d_in[6];
    const float* bv      = (const float*)d_in[7];
    const float* Wa      = (const float*)d_in[8];
    const float* ba      = (const float*)d_in[9];
    const float* rel_att = (const float*)d_in[10];
    const float* rel_msg = (const float*)d_in[11];
    const float* rel_pri = (const float*)d_in[12];
    const float* skip    = (const float*)d_in[13];
    const int*   src0    = (const int*)d_in[14];
    const int*   dst0    = (const int*)d_in[15];
    const int*   src1    = (const int*)d_in[16];
    const int*   dst1    = (const int*)d_in[17];
    const int*   src2    = (const int*)d_in[18];
    const int*   dst2    = (const int*)d_in[19];

    int M  = in_sizes[0] / HID;
    int E0 = in_sizes[14];
    int E1 = in_sizes[16];
    int E2 = in_sizes[18];
    float* out = (float*)d_out;

    cudaFuncSetAttribute(gemm_mma, cudaFuncAttributeMaxDynamicSharedMemorySize, SMEM_TOT);

    float *qbuf, *tmbuf, *bcbuf, *histf;
    __half *kbuf, *vbuf, *wimg;
    cudaGetSymbolAddress((void**)&qbuf,  g_q);
    cudaGetSymbolAddress((void**)&kbuf,  g_k);
    cudaGetSymbolAddress((void**)&vbuf,  g_v);
    cudaGetSymbolAddress((void**)&tmbuf, g_tm);
    cudaGetSymbolAddress((void**)&bcbuf, g_bc);
    cudaGetSymbolAddress((void**)&wimg,  g_Wimg);
    cudaGetSymbolAddress((void**)&histf, g_hist);

    float* q0 = qbuf;                float* q1 = qbuf + (size_t)NNODES * HID;
    __half* k0 = kbuf;               __half* k1 = kbuf + (size_t)NNODES * HID;
    __half* k2 = kbuf + 2 * (size_t)NNODES * HID;
    __half* v0 = vbuf;               __half* v1 = vbuf + (size_t)NNODES * HID;
    __half* v2 = vbuf + 2 * (size_t)NNODES * HID;
    float* tm0 = tmbuf;              float* tm1 = tmbuf + (size_t)NNODES * HID;

    #define WIMG(m) (wimg + (size_t)(m) * IMG_ELEMS)

    int gb = (M + 127) / 128;
    int ET = E0 + E1 + E2;

    // 1-3: weight prep + hist zero
    prep_comb<<<dim3(6, 129), 128>>>(Wk, bk, Wv, bv, rel_att, rel_msg);
    convertW<<<(10 * HID * HID + 255) / 256, 256>>>(Wq, Wa);
    zero_kernel<<<(3 * NNODES / 4 + 255) / 256, 256>>>(histf, 3 * NNODES / 4);

    // 4-5: projection GEMMs (position 4 => gemm b0 is the ncu-profiled launch)
    {
        GemmBatch b0 = {};
        b0.nsets = 3;
        b0.s[0] = { WIMG(6), bq,            q0,      nullptr };
        b0.s[1] = { WIMG(0), bcbuf + 0*HID, nullptr, k0 };
        b0.s[2] = { WIMG(1), bcbuf + 1*HID, nullptr, v0 };
        b0.skipv = nullptr; b0.res = nullptr;
        gemm_mma<<<gb, 256, SMEM_TOT>>>(h0, b0, M);

        GemmBatch b1 = {};
        b1.nsets = 5;
        b1.s[0] = { WIMG(7), bq + HID,      q1,      nullptr };
        b1.s[1] = { WIMG(2), bcbuf + 2*HID, nullptr, k1 };
        b1.s[2] = { WIMG(3), bcbuf + 3*HID, nullptr, v1 };
        b1.s[3] = { WIMG(4), bcbuf + 4*HID, nullptr, k2 };
        b1.s[4] = { WIMG(5), bcbuf + 5*HID, nullptr, v2 };
        b1.skipv = nullptr; b1.res = nullptr;
        gemm_mma<<<gb, 256, SMEM_TOT>>>(h1, b1, M);
    }

    // 6-8: CSR build
    hist_all<<<(ET + 255) / 256, 256>>>(dst0, dst1, dst2, E0, E1, E2);
    scan_kernel<<<3, 1024>>>();
    scatter_all<<<(ET + 255) / 256, 256>>>(src0, dst0, src1, dst1, src2, dst2,
                                           E0, E1, E2);

    // 9: fused aggregation
    agg_all<<<2 * (NNODES / 8), 256>>>(q0, q1, k0, v0, k1, v1, k2, v2,
                                       rel_pri, tm0, tm1);

    // 10-11: output GEMMs with skip blend
    {
        GemmBatch o0 = {};
        o0.nsets = 1;
        o0.s[0] = { WIMG(8), ba, out, nullptr };
        o0.skipv = skip + 0; o0.res = h0;
        gemm_mma<<<gb, 256, SMEM_TOT>>>(tm0, o0, M);

        GemmBatch o1 = {};
        o1.nsets = 1;
        o1.s[0] = { WIMG(9), ba + HID, out + (size_t)M * HID, nullptr };
        o1.skipv = skip + 1; o1.res = h1;
        gemm_mma<<<gb, 256, SMEM_TOT>>>(tm1, o1, M);
    }
}